// round 7
// baseline (speedup 1.0000x reference)
#include <cuda_runtime.h>
#include <cuda_fp16.h>
#include <math.h>
#include <stdint.h>

// ---------------- problem constants ----------------
#define NB   16
#define NV   2048
#define NRC  32
#define NSC  256
#define NEC  512
#define NOUT 12
#define NLAY 8
#define NN   (NV*NV)
#define XBUF (NB*NRC*13*NV)
#define HBUF (NB*NRC*12*NV)

// ---------------- device scratch ----------------
__device__ float  g_adp [NN];
__device__ __half g_bt  [6*NN];          // fp16 transposed supports [z][n][k]; z=3..5 are squares
__device__ __half g_af  [3*NN];          // fp16 straight supports [z][k][m]
__device__ float  g_xa  [XBUF];
__device__ float  g_xb  [XBUF];
__device__ __half g_gx  [HBUF];
__device__ __half g_H   [6*HBUF];
__device__ float  g_skip[NB*NSC*NV];
__device__ __half g_skt [NB*NV*NSC];
__device__ float  g_e1  [NB*NV*NEC];
__device__ __half g_w1r [NEC*NSC];       // fp16 e1w, already [n][k]

// ---------------- helpers ----------------
__device__ __forceinline__ float tanh_fast(float x) {
    float y; asm("tanh.approx.f32 %0, %1;" : "=f"(y) : "f"(x));
    return y;
}
__device__ __forceinline__ uint32_t smem_u32(const void* p) {
    uint32_t a;
    asm("{ .reg .u64 t; cvta.to.shared.u64 t, %1; cvt.u32.u64 %0, t; }" : "=r"(a) : "l"(p));
    return a;
}
__device__ __forceinline__ void cp_async16(uint32_t dst, const void* src) {
    asm volatile("cp.async.cg.shared.global [%0], [%1], 16;" :: "r"(dst), "l"(src));
}
#define CP_COMMIT() asm volatile("cp.async.commit_group;" ::: "memory")

__device__ __forceinline__ void mma_f16_16x8x16(
    float& d0, float& d1, float& d2, float& d3,
    uint32_t a0, uint32_t a1, uint32_t a2, uint32_t a3,
    uint32_t b0, uint32_t b1)
{
    asm volatile(
        "mma.sync.aligned.m16n8k16.row.col.f32.f16.f16.f32 "
        "{%0,%1,%2,%3}, {%4,%5,%6,%7}, {%8,%9}, {%0,%1,%2,%3};"
        : "+f"(d0), "+f"(d1), "+f"(d2), "+f"(d3)
        : "r"(a0), "r"(a1), "r"(a2), "r"(a3), "r"(b0), "r"(b1));
}

// ---------------- fp16 HMMA GEMM: C[M,N] = X[M,K] @ B[N,K]^T ----------------
// CTA tile 128x128, BK=64, 8 warps (4m x 2n), warp tile 32x64, 3-stage cp.async.
// Per-z offsets: X += z*sX, B += z*sB; C offset = lut? LUT(z) : z, times sC.
// flags: bit0 relu, bit2 fp16 output.
#define BM 128
#define BN 128
#define BK 64
#define KPAD_H 72
#define STG_H (BM*KPAD_H)
#define NSTAGE 3
#define GSMEM (NSTAGE*2*STG_H*2)

__global__ void __launch_bounds__(256) mma_gemm(
    const __half* __restrict__ X, const __half* __restrict__ B, void* __restrict__ Cv,
    long sX, long sB, long sC, int lut,
    int lda, int ldb, int ldc, int nkt,
    const float* __restrict__ bias, int flags)
{
    extern __shared__ __half sm[];

    int z = blockIdx.z;
    X += (size_t)z*sX;
    B += (size_t)z*sB;
    long coff = lut ? (long)((z < 3) ? 2*z : 2*z - 5) : (long)z;
    int m0 = blockIdx.y*BM, n0 = blockIdx.x*BN;

    int tid = threadIdx.x, wid = tid >> 5, lane = tid & 31;
    int wm = wid & 3, wn = wid >> 2;
    int lq = lane >> 2, lr = lane & 3;

    uint32_t sbase = smem_u32(sm);

    auto load_stage = [&](int s, int k0) {
        uint32_t da = sbase + (uint32_t)(s*2*STG_H)*2;
        uint32_t db = da + (uint32_t)STG_H*2;
        const __half* xs = X + (size_t)m0*lda + k0;
        const __half* bs = B + (size_t)n0*ldb + k0;
        #pragma unroll
        for (int i = 0; i < 4; i++) {
            int l = tid + i*256;
            int row = l >> 3, seg = l & 7;
            uint32_t off = (uint32_t)(row*KPAD_H + seg*8)*2;
            cp_async16(da + off, xs + (size_t)row*lda + seg*8);
            cp_async16(db + off, bs + (size_t)row*ldb + seg*8);
        }
    };

    float acc[2][8][4];
    #pragma unroll
    for (int mt = 0; mt < 2; mt++)
        #pragma unroll
        for (int nt = 0; nt < 8; nt++)
            #pragma unroll
            for (int k = 0; k < 4; k++) acc[mt][nt][k] = 0.f;

    load_stage(0, 0);  CP_COMMIT();
    if (nkt > 1) load_stage(1, BK);
    CP_COMMIT();

    int ra = wm*32 + lq;
    int rb = wn*64 + lq;

    for (int kt = 0; kt < nkt; kt++) {
        asm volatile("cp.async.wait_group 1;" ::: "memory");
        __syncthreads();

        if (kt + 2 < nkt) load_stage((kt+2) % NSTAGE, (kt+2)*BK);
        CP_COMMIT();

        const __half* Aslab = sm + (kt % NSTAGE)*2*STG_H;
        const __half* Bslab = Aslab + STG_H;

        uint32_t a[2][2][4], b[2][8][2];
        #pragma unroll
        for (int mt = 0; mt < 2; mt++) {
            const __half* ap = Aslab + (ra + mt*16)*KPAD_H + 2*lr;
            a[0][mt][0] = *(const uint32_t*)(ap);
            a[0][mt][1] = *(const uint32_t*)(ap + 8*KPAD_H);
            a[0][mt][2] = *(const uint32_t*)(ap + 8);
            a[0][mt][3] = *(const uint32_t*)(ap + 8*KPAD_H + 8);
        }
        #pragma unroll
        for (int nt = 0; nt < 8; nt++) {
            const __half* bp = Bslab + (rb + nt*8)*KPAD_H + 2*lr;
            b[0][nt][0] = *(const uint32_t*)(bp);
            b[0][nt][1] = *(const uint32_t*)(bp + 8);
        }

        #pragma unroll
        for (int k16 = 0; k16 < BK/16; k16++) {
            int cur = k16 & 1, nxt = cur ^ 1;
            if (k16 + 1 < BK/16) {
                int kk = (k16 + 1)*16;
                #pragma unroll
                for (int mt = 0; mt < 2; mt++) {
                    const __half* ap = Aslab + (ra + mt*16)*KPAD_H + kk + 2*lr;
                    a[nxt][mt][0] = *(const uint32_t*)(ap);
                    a[nxt][mt][1] = *(const uint32_t*)(ap + 8*KPAD_H);
                    a[nxt][mt][2] = *(const uint32_t*)(ap + 8);
                    a[nxt][mt][3] = *(const uint32_t*)(ap + 8*KPAD_H + 8);
                }
                #pragma unroll
                for (int nt = 0; nt < 8; nt++) {
                    const __half* bp = Bslab + (rb + nt*8)*KPAD_H + kk + 2*lr;
                    b[nxt][nt][0] = *(const uint32_t*)(bp);
                    b[nxt][nt][1] = *(const uint32_t*)(bp + 8);
                }
            }
            #pragma unroll
            for (int mt = 0; mt < 2; mt++)
                #pragma unroll
                for (int nt = 0; nt < 8; nt++)
                    mma_f16_16x8x16(acc[mt][nt][0], acc[mt][nt][1], acc[mt][nt][2], acc[mt][nt][3],
                                    a[cur][mt][0], a[cur][mt][1], a[cur][mt][2], a[cur][mt][3],
                                    b[cur][nt][0], b[cur][nt][1]);
        }
    }

    int rowa = m0 + wm*32 + lq;
    int colb = n0 + wn*64 + 2*lr;
    if (flags & 4) {
        __half* Ch = (__half*)Cv + (size_t)coff*sC;
        #pragma unroll
        for (int mt = 0; mt < 2; mt++) {
            #pragma unroll
            for (int nt = 0; nt < 8; nt++) {
                __half2 h0 = __floats2half2_rn(acc[mt][nt][0], acc[mt][nt][1]);
                __half2 h1 = __floats2half2_rn(acc[mt][nt][2], acc[mt][nt][3]);
                *(__half2*)(Ch + (size_t)(rowa + mt*16)*ldc + colb + nt*8) = h0;
                *(__half2*)(Ch + (size_t)(rowa + mt*16 + 8)*ldc + colb + nt*8) = h1;
            }
        }
    } else {
        float* Cf = (float*)Cv + (size_t)coff*sC;
        #pragma unroll
        for (int mt = 0; mt < 2; mt++) {
            #pragma unroll
            for (int nt = 0; nt < 8; nt++) {
                float v0 = acc[mt][nt][0], v1 = acc[mt][nt][1];
                float v2 = acc[mt][nt][2], v3 = acc[mt][nt][3];
                if (bias) {
                    float b0 = bias[colb + nt*8], b1 = bias[colb + nt*8 + 1];
                    v0 += b0; v1 += b1; v2 += b0; v3 += b1;
                }
                if (flags & 1) {
                    v0 = fmaxf(v0, 0.f); v1 = fmaxf(v1, 0.f);
                    v2 = fmaxf(v2, 0.f); v3 = fmaxf(v3, 0.f);
                }
                float2 w0; w0.x = v0; w0.y = v1;
                float2 w1; w1.x = v2; w1.y = v3;
                *(float2*)(Cf + (size_t)(rowa + mt*16)*ldc + colb + nt*8) = w0;
                *(float2*)(Cf + (size_t)(rowa + mt*16 + 8)*ldc + colb + nt*8) = w1;
            }
        }
    }
}

// ---------------- adp = softmax(relu(nv1 @ nv2), axis=1) ----------------
__global__ void adp_kernel(const float* __restrict__ nv1, const float* __restrict__ nv2)
{
    int row = blockIdx.x;
    int tid = threadIdx.x;
    __shared__ float v1[10];
    __shared__ float red[256];
    if (tid < 10) v1[tid] = nv1[row*10 + tid];
    __syncthreads();
    float vals[8];
    float mx = -1e30f;
    #pragma unroll
    for (int j = 0; j < 8; j++) {
        int col = tid + j*256;
        float s = 0.f;
        #pragma unroll
        for (int k = 0; k < 10; k++) s += v1[k]*nv2[k*NV + col];
        s = fmaxf(s, 0.f);
        vals[j] = s;
        mx = fmaxf(mx, s);
    }
    red[tid] = mx; __syncthreads();
    for (int s2 = 128; s2 > 0; s2 >>= 1) {
        if (tid < s2) red[tid] = fmaxf(red[tid], red[tid+s2]);
        __syncthreads();
    }
    mx = red[0];
    __syncthreads();
    float sum = 0.f;
    #pragma unroll
    for (int j = 0; j < 8; j++) { vals[j] = expf(vals[j] - mx); sum += vals[j]; }
    red[tid] = sum; __syncthreads();
    for (int s2 = 128; s2 > 0; s2 >>= 1) {
        if (tid < s2) red[tid] += red[tid+s2];
        __syncthreads();
    }
    float inv = 1.f/red[0];
    #pragma unroll
    for (int j = 0; j < 8; j++) g_adp[row*NV + tid + j*256] = vals[j]*inv;
}

// ---------------- build fp16 transposed + straight supports ----------------
__global__ void bt_kernel(const float* __restrict__ A)
{
    __shared__ float tile[32][33];
    int z = blockIdx.z;
    const float* S = (z < 2) ? (A + (size_t)z*NN) : g_adp;
    int r0 = blockIdx.y*32, c0 = blockIdx.x*32;
    int x = threadIdx.x & 31, y = threadIdx.x >> 5;
    #pragma unroll
    for (int i = 0; i < 32; i += 8) {
        float v = S[(size_t)(r0 + y + i)*NV + c0 + x];
        tile[y+i][x] = v;
        g_af[((size_t)z*NV + r0 + y + i)*NV + c0 + x] = __float2half(v);
    }
    __syncthreads();
    #pragma unroll
    for (int i = 0; i < 32; i += 8)
        g_bt[((size_t)z*NV + c0 + y + i)*NV + r0 + x] = __float2half(tile[x][y+i]);
}

// ---------------- pad + start 1x1 conv ----------------
__global__ void start_kernel(const float* __restrict__ x,
                             const float* __restrict__ sw, const float* __restrict__ sb)
{
    int v = blockIdx.x*256 + threadIdx.x;
    int t = blockIdx.y, b = blockIdx.z;
    float in0 = 0.f, in1 = 0.f;
    if (t > 0) {
        in0 = x[((b*2+0)*NV + v)*12 + (t-1)];
        in1 = x[((b*2+1)*NV + v)*12 + (t-1)];
    }
    #pragma unroll
    for (int o = 0; o < NRC; o++) {
        g_xa[((b*NRC+o)*13 + t)*NV + v] = sb[o] + sw[o*2]*in0 + sw[o*2+1]*in1;
    }
}

// ---------------- gated dilated conv -> fp16 gx (packed float4 weights) ----------------
__global__ __launch_bounds__(256) void gated_kernel(
    const float* __restrict__ fw, const float* __restrict__ fb,
    const float* __restrict__ gw, const float* __restrict__ gb,
    int layer, int Tin, int d, int parity)
{
    const float* xin = parity ? g_xb : g_xa;
    int Tout = Tin - d;
    int v = blockIdx.x*256 + threadIdx.x;
    int t = blockIdx.y, b = blockIdx.z;

    __shared__ float4 swp[NRC*NRC];          // {fw0, fw1, gw0, gw1}
    __shared__ float sfb[NRC], sgb[NRC];
    const float* fwl = fw + layer*NRC*NRC*2;
    const float* gwl = gw + layer*NRC*NRC*2;
    for (int i = threadIdx.x; i < NRC*NRC; i += 256) {
        float2 fv = *(const float2*)(fwl + i*2);
        float2 gv = *(const float2*)(gwl + i*2);
        swp[i] = make_float4(fv.x, fv.y, gv.x, gv.y);
    }
    if (threadIdx.x < NRC) {
        sfb[threadIdx.x] = fb[layer*NRC + threadIdx.x];
        sgb[threadIdx.x] = gb[layer*NRC + threadIdx.x];
    }
    __syncthreads();

    float x0[NRC], x1[NRC];
    #pragma unroll
    for (int c = 0; c < NRC; c++) {
        x0[c] = xin[((b*NRC+c)*Tin + t    )*NV + v];
        x1[c] = xin[((b*NRC+c)*Tin + t + d)*NV + v];
    }
    #pragma unroll 4
    for (int o = 0; o < NRC; o++) {
        float f = sfb[o], g = sgb[o];
        #pragma unroll
        for (int c = 0; c < NRC; c++) {
            float4 w = swp[o*NRC + c];
            f += w.x*x0[c] + w.y*x1[c];
            g += w.z*x0[c] + w.w*x1[c];
        }
        float filt = tanh_fast(f);
        float gate = 0.5f*tanh_fast(0.5f*g) + 0.5f;
        g_gx[((b*NRC+o)*Tout + t)*NV + v] = __float2half(filt*gate);
    }
}

// ---------------- skip conv (last time step only) ----------------
__global__ __launch_bounds__(256) void skip_kernel(
    const float* __restrict__ sw, const float* __restrict__ sb, int layer, int Tout)
{
    int v  = blockIdx.x*256 + threadIdx.x;
    int og = blockIdx.y*8;
    int b  = blockIdx.z;
    const float* swl = sw + layer*NSC*NRC;
    const float* sbl = sb + layer*NSC;
    __shared__ float w[8][NRC];
    {
        int j = threadIdx.x / NRC, c = threadIdx.x % NRC;
        w[j][c] = swl[(og + j)*NRC + c];
    }
    __syncthreads();
    float acc[8];
    #pragma unroll
    for (int j = 0; j < 8; j++) acc[j] = sbl[og + j];
    #pragma unroll
    for (int c = 0; c < NRC; c++) {
        float gv = __half2float(g_gx[((b*NRC+c)*Tout + (Tout-1))*NV + v]);
        #pragma unroll
        for (int j = 0; j < 8; j++) acc[j] += w[j][c]*gv;
    }
    #pragma unroll
    for (int j = 0; j < 8; j++) g_skip[(b*NSC + og + j)*NV + v] += acc[j];
}

// ---------------- gcn 1x1 conv + bias + residual + BN (transposed weight smem) ----------------
__global__ __launch_bounds__(256) void gcn_kernel(
    const float* __restrict__ gw, const float* __restrict__ gb,
    const float* __restrict__ bng, const float* __restrict__ bnb,
    const float* __restrict__ bnm, const float* __restrict__ bnv,
    int layer, int Tin, int d, int parity)
{
    int Tout = Tin - d;
    const float* xin  = parity ? g_xb : g_xa;
    float*       xout = parity ? g_xa : g_xb;

    __shared__ float ws[224*32];     // ws[gc][og*8 + j] = w[og + j*4][gc]
    __shared__ float hs[NRC][64];
    __shared__ float s_inv[NRC], s_beta[NRC], s_mean[NRC], s_gb[NRC];

    const float* gwl = gw + layer*NRC*224;
    for (int i = threadIdx.x; i < 224*32; i += 256) {
        int gc = i >> 5, q = i & 31;
        int og2 = q >> 3, j = q & 7;
        ws[i] = gwl[(og2 + j*4)*224 + gc];
    }
    if (threadIdx.x < NRC) {
        int o = threadIdx.x;
        s_inv [o] = bng[layer*NRC+o]*rsqrtf(bnv[layer*NRC+o] + 1e-5f);
        s_beta[o] = bnb[layer*NRC+o];
        s_mean[o] = bnm[layer*NRC+o];
        s_gb  [o] = gb [layer*NRC+o];
    }

    int vi = threadIdx.x & 63;
    int og = threadIdx.x >> 6;
    int v0 = blockIdx.x*64;
    int t = blockIdx.y, b = blockIdx.z;

    float acc[8];
    #pragma unroll
    for (int j = 0; j < 8; j++) acc[j] = 0.f;

    for (int g = 0; g < 7; g++) {
        const __half* H = (g == 0) ? g_gx : (g_H + (size_t)(g-1)*HBUF);
        __syncthreads();
        for (int i = threadIdx.x; i < NRC*64; i += 256) {
            int c = i >> 6, vv = i & 63;
            hs[c][vv] = __half2float(H[((b*NRC+c)*Tout + t)*NV + v0 + vv]);
        }
        __syncthreads();
        #pragma unroll
        for (int c = 0; c < 32; c++) {
            float hv = hs[c][vi];
            const float4* wp = (const float4*)&ws[(g*32 + c)*32 + og*8];
            float4 wa = wp[0], wb = wp[1];
            acc[0] += wa.x*hv; acc[1] += wa.y*hv; acc[2] += wa.z*hv; acc[3] += wa.w*hv;
            acc[4] += wb.x*hv; acc[5] += wb.y*hv; acc[6] += wb.z*hv; acc[7] += wb.w*hv;
        }
    }

    #pragma unroll
    for (int j = 0; j < 8; j++) {
        int o = og + j*4;
        float val = acc[j] + s_gb[o]
                  + xin[((b*NRC+o)*Tin + (t + d))*NV + v0 + vi];
        val = (val - s_mean[o])*s_inv[o] + s_beta[o];
        xout[((b*NRC+o)*Tout + t)*NV + v0 + vi] = val;
    }
}

// ---------------- relu + transpose skip -> fp16 [b*v][c] ----------------
__global__ void skt_kernel()
{
    __shared__ float tile[32][33];
    int b  = blockIdx.z;
    int c0 = blockIdx.y*32, v0 = blockIdx.x*32;
    int x = threadIdx.x % 32, y = threadIdx.x / 32;
    #pragma unroll
    for (int i = 0; i < 32; i += 8)
        tile[y+i][x] = g_skip[(b*NSC + c0 + y + i)*NV + v0 + x];
    __syncthreads();
    #pragma unroll
    for (int i = 0; i < 32; i += 8)
        g_skt[((size_t)b*NV + v0 + y + i)*NSC + c0 + x] = __float2half(fmaxf(tile[x][y+i], 0.f));
}

// ---------------- fp16 end1 weights ----------------
__global__ void w1r_kernel(const float* __restrict__ e1w)
{
    int idx = blockIdx.x*256 + threadIdx.x;
    g_w1r[idx] = __float2half(e1w[idx]);
}

// ---------------- end2 ----------------
__global__ __launch_bounds__(256) void end2_kernel(
    const float* __restrict__ e2w, const float* __restrict__ e2b, float* __restrict__ out)
{
    __shared__ float w[NOUT*NEC];
    __shared__ float sb[NOUT];
    for (int i = threadIdx.x; i < NOUT*NEC; i += 256) w[i] = e2w[i];
    if (threadIdx.x < NOUT) sb[threadIdx.x] = e2b[threadIdx.x];
    __syncthreads();

    int warp = threadIdx.x >> 5, lane = threadIdx.x & 31;
    int row = blockIdx.x*8 + warp;
    const float* e1r = g_e1 + (size_t)row*NEC;
    float r[16];
    #pragma unroll
    for (int k = 0; k < 16; k++) r[k] = e1r[lane + k*32];
    int b = row >> 11, v = row & (NV-1);
    #pragma unroll
    for (int o = 0; o < NOUT; o++) {
        float s = 0.f;
        #pragma unroll
        for (int k = 0; k < 16; k++) s += r[k]*w[o*NEC + lane + k*32];
        #pragma unroll
        for (int off = 16; off; off >>= 1) s += __shfl_xor_sync(0xffffffffu, s, off);
        if (lane == 0) out[((size_t)b*NOUT + o)*NV + v] = s + sb[o];
    }
}

// ---------------- launch ----------------
extern "C" void kernel_launch(void* const* d_in, const int* in_sizes, int n_in,
                              void* d_out, int out_size)
{
    (void)in_sizes; (void)n_in; (void)out_size;
    const float* x    = (const float*)d_in[0];
    const float* A    = (const float*)d_in[1];
    const float* nv1  = (const float*)d_in[2];
    const float* nv2  = (const float*)d_in[3];
    const float* fw   = (const float*)d_in[4];
    const float* fb   = (const float*)d_in[5];
    const float* gw   = (const float*)d_in[6];
    const float* gb   = (const float*)d_in[7];
    const float* sw   = (const float*)d_in[8];
    const float* sb   = (const float*)d_in[9];
    const float* gcnw = (const float*)d_in[10];
    const float* gcnb = (const float*)d_in[11];
    const float* bng  = (const float*)d_in[12];
    const float* bnb  = (const float*)d_in[13];
    const float* bnm  = (const float*)d_in[14];
    const float* bnv  = (const float*)d_in[15];
    const float* stw  = (const float*)d_in[16];
    const float* stb  = (const float*)d_in[17];
    const float* e1w  = (const float*)d_in[18];
    const float* e1b  = (const float*)d_in[19];
    const float* e2w  = (const float*)d_in[20];
    const float* e2b  = (const float*)d_in[21];

    __half *p_gx, *p_H, *p_skt, *p_w1r, *p_bt, *p_af;
    float  *p_skip, *p_e1;
    cudaGetSymbolAddress((void**)&p_gx,   g_gx);
    cudaGetSymbolAddress((void**)&p_H,    g_H);
    cudaGetSymbolAddress((void**)&p_skip, g_skip);
    cudaGetSymbolAddress((void**)&p_skt,  g_skt);
    cudaGetSymbolAddress((void**)&p_e1,   g_e1);
    cudaGetSymbolAddress((void**)&p_w1r,  g_w1r);
    cudaGetSymbolAddress((void**)&p_bt,   g_bt);
    cudaGetSymbolAddress((void**)&p_af,   g_af);

    cudaFuncSetAttribute(mma_gemm, cudaFuncAttributeMaxDynamicSharedMemorySize, GSMEM);

    adp_kernel<<<NV, 256>>>(nv1, nv2);
    bt_kernel<<<dim3(NV/32, NV/32, 3), 256>>>(A);
    // squares: bt2_z[n][k] = A_z^2[k][n] = sum_m bt_z[n][m] * af_z[k][m]
    mma_gemm<<<dim3(NV/BN, NV/BM, 3), 256, GSMEM>>>(
        p_bt, p_af, p_bt + 3*(size_t)NN,
        (long)NN, (long)NN, (long)NN, 0,
        NV, NV, NV, NV/BK, nullptr, 4);
    start_kernel<<<dim3(NV/256, 13, NB), 256>>>(x, stw, stb);
    cudaMemsetAsync(p_skip, 0, (size_t)NB*NSC*NV*sizeof(float));

    const int dil[NLAY] = {1,2,1,2,1,2,1,2};
    int Tin = 13, parity = 0;
    for (int i = 0; i < NLAY; i++) {
        int d = dil[i], Tout = Tin - d;
        gated_kernel<<<dim3(NV/256, Tout, NB), 256>>>(fw, fb, gw, gb, i, Tin, d, parity);
        skip_kernel<<<dim3(NV/256, NSC/8, NB), 256>>>(sw, sb, i, Tout);

        if (i < NLAY-1) {   // last layer's gcn output is dead code
            int M = NB*NRC*Tout;
            // 6 independent GEMMs: z=0..2 hop1 (A), z=3..5 hop2 (A^2); C via LUT -> H0..H5
            mma_gemm<<<dim3(NV/BN, M/BM, 6), 256, GSMEM>>>(
                p_gx, p_bt, p_H,
                0L, (long)NN, (long)HBUF, 1,
                NV, NV, NV, NV/BK, nullptr, 4);
            gcn_kernel<<<dim3(NV/64, Tout, NB), 256>>>(gcnw, gcnb, bng, bnb, bnm, bnv,
                                                       i, Tin, d, parity);
        }
        parity ^= 1;
        Tin = Tout;
    }

    skt_kernel<<<dim3(NV/32, NSC/32, NB), 256>>>();
    w1r_kernel<<<(NEC*NSC)/256, 256>>>(e1w);
    mma_gemm<<<dim3(NEC/BN, (NB*NV)/BM, 1), 256, GSMEM>>>(
        p_skt, p_w1r, p_e1,
        0L, 0L, 0L, 0,
        NSC, NSC, NEC, NSC/BK, e1b, 1);
    end2_kernel<<<(NB*NV)/8, 256>>>(e2w, e2b, (float*)d_out);
}

// round 8
// speedup vs baseline: 1.0294x; 1.0294x over previous
#include <cuda_runtime.h>
#include <cuda_fp16.h>
#include <math.h>
#include <stdint.h>

// ---------------- problem constants ----------------
#define NB   16
#define NV   2048
#define NRC  32
#define NSC  256
#define NEC  512
#define NOUT 12
#define NLAY 8
#define NN   (NV*NV)
#define XBUF (NB*NRC*13*NV)
#define HBUF (NB*NRC*12*NV)

// ---------------- device scratch ----------------
__device__ float  g_adp [NN];
__device__ __half g_bt  [3*NN];          // fp16 transposed supports [z][n][k]
__device__ float  g_xa  [XBUF];
__device__ float  g_xb  [XBUF];
__device__ __half g_gx  [HBUF];
__device__ __half g_H   [6*HBUF];
__device__ float  g_skip[NB*NSC*NV];
__device__ __half g_skt [NB*NV*NSC];
__device__ float  g_e1  [NB*NV*NEC];
__device__ __half g_w1r [NEC*NSC];       // fp16 e1w, already [n][k]

// ---------------- helpers ----------------
__device__ __forceinline__ float tanh_fast(float x) {
    float y; asm("tanh.approx.f32 %0, %1;" : "=f"(y) : "f"(x));
    return y;
}
__device__ __forceinline__ uint32_t smem_u32(const void* p) {
    uint32_t a;
    asm("{ .reg .u64 t; cvta.to.shared.u64 t, %1; cvt.u32.u64 %0, t; }" : "=r"(a) : "l"(p));
    return a;
}
__device__ __forceinline__ void cp_async16(uint32_t dst, const void* src) {
    asm volatile("cp.async.cg.shared.global [%0], [%1], 16;" :: "r"(dst), "l"(src));
}
#define CP_COMMIT() asm volatile("cp.async.commit_group;" ::: "memory")

__device__ __forceinline__ void mma_f16_16x8x16(
    float& d0, float& d1, float& d2, float& d3,
    uint32_t a0, uint32_t a1, uint32_t a2, uint32_t a3,
    uint32_t b0, uint32_t b1)
{
    asm volatile(
        "mma.sync.aligned.m16n8k16.row.col.f32.f16.f16.f32 "
        "{%0,%1,%2,%3}, {%4,%5,%6,%7}, {%8,%9}, {%0,%1,%2,%3};"
        : "+f"(d0), "+f"(d1), "+f"(d2), "+f"(d3)
        : "r"(a0), "r"(a1), "r"(a2), "r"(a3), "r"(b0), "r"(b1));
}

// ---------------- fp16 HMMA GEMM: C[M,N] = X[M,K] @ B[N,K]^T ----------------
// CTA tile 128x128, BK=64, 8 warps (4m x 2n), warp tile 32x64, 3-stage cp.async.
// Per-z strides: X += z*sX, B += z*sB, C += z*sC. flags: bit0 relu, bit2 fp16 out.
#define BM 128
#define BN 128
#define BK 64
#define KPAD_H 72
#define STG_H (BM*KPAD_H)
#define NSTAGE 3
#define GSMEM (NSTAGE*2*STG_H*2)

__global__ void __launch_bounds__(256) mma_gemm(
    const __half* __restrict__ X, const __half* __restrict__ B, void* __restrict__ Cv,
    long sX, long sB, long sC,
    int lda, int ldb, int ldc, int nkt,
    const float* __restrict__ bias, int flags)
{
    extern __shared__ __half sm[];

    int z = blockIdx.z;
    X += (size_t)z*sX;
    B += (size_t)z*sB;
    int m0 = blockIdx.y*BM, n0 = blockIdx.x*BN;

    int tid = threadIdx.x, wid = tid >> 5, lane = tid & 31;
    int wm = wid & 3, wn = wid >> 2;
    int lq = lane >> 2, lr = lane & 3;

    uint32_t sbase = smem_u32(sm);

    auto load_stage = [&](int s, int k0) {
        uint32_t da = sbase + (uint32_t)(s*2*STG_H)*2;
        uint32_t db = da + (uint32_t)STG_H*2;
        const __half* xs = X + (size_t)m0*lda + k0;
        const __half* bs = B + (size_t)n0*ldb + k0;
        #pragma unroll
        for (int i = 0; i < 4; i++) {
            int l = tid + i*256;
            int row = l >> 3, seg = l & 7;
            uint32_t off = (uint32_t)(row*KPAD_H + seg*8)*2;
            cp_async16(da + off, xs + (size_t)row*lda + seg*8);
            cp_async16(db + off, bs + (size_t)row*ldb + seg*8);
        }
    };

    float acc[2][8][4];
    #pragma unroll
    for (int mt = 0; mt < 2; mt++)
        #pragma unroll
        for (int nt = 0; nt < 8; nt++)
            #pragma unroll
            for (int k = 0; k < 4; k++) acc[mt][nt][k] = 0.f;

    load_stage(0, 0);  CP_COMMIT();
    if (nkt > 1) load_stage(1, BK);
    CP_COMMIT();

    int ra = wm*32 + lq;
    int rb = wn*64 + lq;

    for (int kt = 0; kt < nkt; kt++) {
        asm volatile("cp.async.wait_group 1;" ::: "memory");
        __syncthreads();

        if (kt + 2 < nkt) load_stage((kt+2) % NSTAGE, (kt+2)*BK);
        CP_COMMIT();

        const __half* Aslab = sm + (kt % NSTAGE)*2*STG_H;
        const __half* Bslab = Aslab + STG_H;

        uint32_t a[2][2][4], b[2][8][2];
        #pragma unroll
        for (int mt = 0; mt < 2; mt++) {
            const __half* ap = Aslab + (ra + mt*16)*KPAD_H + 2*lr;
            a[0][mt][0] = *(const uint32_t*)(ap);
            a[0][mt][1] = *(const uint32_t*)(ap + 8*KPAD_H);
            a[0][mt][2] = *(const uint32_t*)(ap + 8);
            a[0][mt][3] = *(const uint32_t*)(ap + 8*KPAD_H + 8);
        }
        #pragma unroll
        for (int nt = 0; nt < 8; nt++) {
            const __half* bp = Bslab + (rb + nt*8)*KPAD_H + 2*lr;
            b[0][nt][0] = *(const uint32_t*)(bp);
            b[0][nt][1] = *(const uint32_t*)(bp + 8);
        }

        #pragma unroll
        for (int k16 = 0; k16 < BK/16; k16++) {
            int cur = k16 & 1, nxt = cur ^ 1;
            if (k16 + 1 < BK/16) {
                int kk = (k16 + 1)*16;
                #pragma unroll
                for (int mt = 0; mt < 2; mt++) {
                    const __half* ap = Aslab + (ra + mt*16)*KPAD_H + kk + 2*lr;
                    a[nxt][mt][0] = *(const uint32_t*)(ap);
                    a[nxt][mt][1] = *(const uint32_t*)(ap + 8*KPAD_H);
                    a[nxt][mt][2] = *(const uint32_t*)(ap + 8);
                    a[nxt][mt][3] = *(const uint32_t*)(ap + 8*KPAD_H + 8);
                }
                #pragma unroll
                for (int nt = 0; nt < 8; nt++) {
                    const __half* bp = Bslab + (rb + nt*8)*KPAD_H + kk + 2*lr;
                    b[nxt][nt][0] = *(const uint32_t*)(bp);
                    b[nxt][nt][1] = *(const uint32_t*)(bp + 8);
                }
            }
            #pragma unroll
            for (int mt = 0; mt < 2; mt++)
                #pragma unroll
                for (int nt = 0; nt < 8; nt++)
                    mma_f16_16x8x16(acc[mt][nt][0], acc[mt][nt][1], acc[mt][nt][2], acc[mt][nt][3],
                                    a[cur][mt][0], a[cur][mt][1], a[cur][mt][2], a[cur][mt][3],
                                    b[cur][nt][0], b[cur][nt][1]);
        }
    }

    int rowa = m0 + wm*32 + lq;
    int colb = n0 + wn*64 + 2*lr;
    if (flags & 4) {
        __half* Ch = (__half*)Cv + (size_t)z*sC;
        #pragma unroll
        for (int mt = 0; mt < 2; mt++) {
            #pragma unroll
            for (int nt = 0; nt < 8; nt++) {
                __half2 h0 = __floats2half2_rn(acc[mt][nt][0], acc[mt][nt][1]);
                __half2 h1 = __floats2half2_rn(acc[mt][nt][2], acc[mt][nt][3]);
                *(__half2*)(Ch + (size_t)(rowa + mt*16)*ldc + colb + nt*8) = h0;
                *(__half2*)(Ch + (size_t)(rowa + mt*16 + 8)*ldc + colb + nt*8) = h1;
            }
        }
    } else {
        float* Cf = (float*)Cv + (size_t)z*sC;
        #pragma unroll
        for (int mt = 0; mt < 2; mt++) {
            #pragma unroll
            for (int nt = 0; nt < 8; nt++) {
                float v0 = acc[mt][nt][0], v1 = acc[mt][nt][1];
                float v2 = acc[mt][nt][2], v3 = acc[mt][nt][3];
                if (bias) {
                    float b0 = bias[colb + nt*8], b1 = bias[colb + nt*8 + 1];
                    v0 += b0; v1 += b1; v2 += b0; v3 += b1;
                }
                if (flags & 1) {
                    v0 = fmaxf(v0, 0.f); v1 = fmaxf(v1, 0.f);
                    v2 = fmaxf(v2, 0.f); v3 = fmaxf(v3, 0.f);
                }
                float2 w0; w0.x = v0; w0.y = v1;
                float2 w1; w1.x = v2; w1.y = v3;
                *(float2*)(Cf + (size_t)(rowa + mt*16)*ldc + colb + nt*8) = w0;
                *(float2*)(Cf + (size_t)(rowa + mt*16 + 8)*ldc + colb + nt*8) = w1;
            }
        }
    }
}

// ---------------- adp = softmax(relu(nv1 @ nv2), axis=1) ----------------
__global__ void adp_kernel(const float* __restrict__ nv1, const float* __restrict__ nv2)
{
    int row = blockIdx.x;
    int tid = threadIdx.x;
    __shared__ float v1[10];
    __shared__ float red[256];
    if (tid < 10) v1[tid] = nv1[row*10 + tid];
    __syncthreads();
    float vals[8];
    float mx = -1e30f;
    #pragma unroll
    for (int j = 0; j < 8; j++) {
        int col = tid + j*256;
        float s = 0.f;
        #pragma unroll
        for (int k = 0; k < 10; k++) s += v1[k]*nv2[k*NV + col];
        s = fmaxf(s, 0.f);
        vals[j] = s;
        mx = fmaxf(mx, s);
    }
    red[tid] = mx; __syncthreads();
    for (int s2 = 128; s2 > 0; s2 >>= 1) {
        if (tid < s2) red[tid] = fmaxf(red[tid], red[tid+s2]);
        __syncthreads();
    }
    mx = red[0];
    __syncthreads();
    float sum = 0.f;
    #pragma unroll
    for (int j = 0; j < 8; j++) { vals[j] = expf(vals[j] - mx); sum += vals[j]; }
    red[tid] = sum; __syncthreads();
    for (int s2 = 128; s2 > 0; s2 >>= 1) {
        if (tid < s2) red[tid] += red[tid+s2];
        __syncthreads();
    }
    float inv = 1.f/red[0];
    #pragma unroll
    for (int j = 0; j < 8; j++) g_adp[row*NV + tid + j*256] = vals[j]*inv;
}

// ---------------- build fp16 transposed supports ----------------
__global__ void bt_kernel(const float* __restrict__ A)
{
    __shared__ float tile[32][33];
    int z = blockIdx.z;
    const float* S = (z < 2) ? (A + (size_t)z*NN) : g_adp;
    int r0 = blockIdx.y*32, c0 = blockIdx.x*32;
    int x = threadIdx.x & 31, y = threadIdx.x >> 5;
    #pragma unroll
    for (int i = 0; i < 32; i += 8)
        tile[y+i][x] = S[(size_t)(r0 + y + i)*NV + c0 + x];
    __syncthreads();
    #pragma unroll
    for (int i = 0; i < 32; i += 8)
        g_bt[((size_t)z*NV + c0 + y + i)*NV + r0 + x] = __float2half(tile[x][y+i]);
}

// ---------------- pad + start 1x1 conv ----------------
__global__ void start_kernel(const float* __restrict__ x,
                             const float* __restrict__ sw, const float* __restrict__ sb)
{
    int v = blockIdx.x*256 + threadIdx.x;
    int t = blockIdx.y, b = blockIdx.z;
    float in0 = 0.f, in1 = 0.f;
    if (t > 0) {
        in0 = x[((b*2+0)*NV + v)*12 + (t-1)];
        in1 = x[((b*2+1)*NV + v)*12 + (t-1)];
    }
    #pragma unroll
    for (int o = 0; o < NRC; o++) {
        g_xa[((b*NRC+o)*13 + t)*NV + v] = sb[o] + sw[o*2]*in0 + sw[o*2+1]*in1;
    }
}

// ---------------- gated dilated conv -> fp16 gx (packed float4 weights) ----------------
__global__ __launch_bounds__(256) void gated_kernel(
    const float* __restrict__ fw, const float* __restrict__ fb,
    const float* __restrict__ gw, const float* __restrict__ gb,
    int layer, int Tin, int d, int parity)
{
    const float* xin = parity ? g_xb : g_xa;
    int Tout = Tin - d;
    int v = blockIdx.x*256 + threadIdx.x;
    int t = blockIdx.y, b = blockIdx.z;

    __shared__ float4 swp[NRC*NRC];          // {fw0, fw1, gw0, gw1}
    __shared__ float sfb[NRC], sgb[NRC];
    const float* fwl = fw + layer*NRC*NRC*2;
    const float* gwl = gw + layer*NRC*NRC*2;
    for (int i = threadIdx.x; i < NRC*NRC; i += 256) {
        float2 fv = *(const float2*)(fwl + i*2);
        float2 gv = *(const float2*)(gwl + i*2);
        swp[i] = make_float4(fv.x, fv.y, gv.x, gv.y);
    }
    if (threadIdx.x < NRC) {
        sfb[threadIdx.x] = fb[layer*NRC + threadIdx.x];
        sgb[threadIdx.x] = gb[layer*NRC + threadIdx.x];
    }
    __syncthreads();

    float x0[NRC], x1[NRC];
    #pragma unroll
    for (int c = 0; c < NRC; c++) {
        x0[c] = xin[((b*NRC+c)*Tin + t    )*NV + v];
        x1[c] = xin[((b*NRC+c)*Tin + t + d)*NV + v];
    }
    #pragma unroll 4
    for (int o = 0; o < NRC; o++) {
        float f = sfb[o], g = sgb[o];
        #pragma unroll
        for (int c = 0; c < NRC; c++) {
            float4 w = swp[o*NRC + c];
            f += w.x*x0[c] + w.y*x1[c];
            g += w.z*x0[c] + w.w*x1[c];
        }
        float filt = tanh_fast(f);
        float gate = 0.5f*tanh_fast(0.5f*g) + 0.5f;
        g_gx[((b*NRC+o)*Tout + t)*NV + v] = __float2half(filt*gate);
    }
}

// ---------------- skip conv (last time step only) ----------------
__global__ __launch_bounds__(256) void skip_kernel(
    const float* __restrict__ sw, const float* __restrict__ sb, int layer, int Tout)
{
    int v  = blockIdx.x*256 + threadIdx.x;
    int og = blockIdx.y*8;
    int b  = blockIdx.z;
    const float* swl = sw + layer*NSC*NRC;
    const float* sbl = sb + layer*NSC;
    __shared__ float w[8][NRC];
    {
        int j = threadIdx.x / NRC, c = threadIdx.x % NRC;
        w[j][c] = swl[(og + j)*NRC + c];
    }
    __syncthreads();
    float acc[8];
    #pragma unroll
    for (int j = 0; j < 8; j++) acc[j] = sbl[og + j];
    #pragma unroll
    for (int c = 0; c < NRC; c++) {
        float gv = __half2float(g_gx[((b*NRC+c)*Tout + (Tout-1))*NV + v]);
        #pragma unroll
        for (int j = 0; j < 8; j++) acc[j] += w[j][c]*gv;
    }
    #pragma unroll
    for (int j = 0; j < 8; j++) g_skip[(b*NSC + og + j)*NV + v] += acc[j];
}

// ---------------- gcn 1x1 conv + bias + residual + BN (transposed weight smem) ----------------
__global__ __launch_bounds__(256) void gcn_kernel(
    const float* __restrict__ gw, const float* __restrict__ gb,
    const float* __restrict__ bng, const float* __restrict__ bnb,
    const float* __restrict__ bnm, const float* __restrict__ bnv,
    int layer, int Tin, int d, int parity)
{
    int Tout = Tin - d;
    const float* xin  = parity ? g_xb : g_xa;
    float*       xout = parity ? g_xa : g_xb;

    __shared__ float ws[224*32];     // ws[gc][og*8 + j] = w[og + j*4][gc]
    __shared__ float hs[NRC][64];
    __shared__ float s_inv[NRC], s_beta[NRC], s_mean[NRC], s_gb[NRC];

    const float* gwl = gw + layer*NRC*224;
    for (int i = threadIdx.x; i < 224*32; i += 256) {
        int gc = i >> 5, q = i & 31;
        int og2 = q >> 3, j = q & 7;
        ws[i] = gwl[(og2 + j*4)*224 + gc];
    }
    if (threadIdx.x < NRC) {
        int o = threadIdx.x;
        s_inv [o] = bng[layer*NRC+o]*rsqrtf(bnv[layer*NRC+o] + 1e-5f);
        s_beta[o] = bnb[layer*NRC+o];
        s_mean[o] = bnm[layer*NRC+o];
        s_gb  [o] = gb [layer*NRC+o];
    }

    int vi = threadIdx.x & 63;
    int og = threadIdx.x >> 6;
    int v0 = blockIdx.x*64;
    int t = blockIdx.y, b = blockIdx.z;

    float acc[8];
    #pragma unroll
    for (int j = 0; j < 8; j++) acc[j] = 0.f;

    for (int g = 0; g < 7; g++) {
        const __half* H = (g == 0) ? g_gx : (g_H + (size_t)(g-1)*HBUF);
        __syncthreads();
        for (int i = threadIdx.x; i < NRC*64; i += 256) {
            int c = i >> 6, vv = i & 63;
            hs[c][vv] = __half2float(H[((b*NRC+c)*Tout + t)*NV + v0 + vv]);
        }
        __syncthreads();
        #pragma unroll
        for (int c = 0; c < 32; c++) {
            float hv = hs[c][vi];
            const float4* wp = (const float4*)&ws[(g*32 + c)*32 + og*8];
            float4 wa = wp[0], wb = wp[1];
            acc[0] += wa.x*hv; acc[1] += wa.y*hv; acc[2] += wa.z*hv; acc[3] += wa.w*hv;
            acc[4] += wb.x*hv; acc[5] += wb.y*hv; acc[6] += wb.z*hv; acc[7] += wb.w*hv;
        }
    }

    #pragma unroll
    for (int j = 0; j < 8; j++) {
        int o = og + j*4;
        float val = acc[j] + s_gb[o]
                  + xin[((b*NRC+o)*Tin + (t + d))*NV + v0 + vi];
        val = (val - s_mean[o])*s_inv[o] + s_beta[o];
        xout[((b*NRC+o)*Tout + t)*NV + v0 + vi] = val;
    }
}

// ---------------- relu + transpose skip -> fp16 [b*v][c] ----------------
__global__ void skt_kernel()
{
    __shared__ float tile[32][33];
    int b  = blockIdx.z;
    int c0 = blockIdx.y*32, v0 = blockIdx.x*32;
    int x = threadIdx.x % 32, y = threadIdx.x / 32;
    #pragma unroll
    for (int i = 0; i < 32; i += 8)
        tile[y+i][x] = g_skip[(b*NSC + c0 + y + i)*NV + v0 + x];
    __syncthreads();
    #pragma unroll
    for (int i = 0; i < 32; i += 8)
        g_skt[((size_t)b*NV + v0 + y + i)*NSC + c0 + x] = __float2half(fmaxf(tile[x][y+i], 0.f));
}

// ---------------- fp16 end1 weights ----------------
__global__ void w1r_kernel(const float* __restrict__ e1w)
{
    int idx = blockIdx.x*256 + threadIdx.x;
    g_w1r[idx] = __float2half(e1w[idx]);
}

// ---------------- end2 ----------------
__global__ __launch_bounds__(256) void end2_kernel(
    const float* __restrict__ e2w, const float* __restrict__ e2b, float* __restrict__ out)
{
    __shared__ float w[NOUT*NEC];
    __shared__ float sb[NOUT];
    for (int i = threadIdx.x; i < NOUT*NEC; i += 256) w[i] = e2w[i];
    if (threadIdx.x < NOUT) sb[threadIdx.x] = e2b[threadIdx.x];
    __syncthreads();

    int warp = threadIdx.x >> 5, lane = threadIdx.x & 31;
    int row = blockIdx.x*8 + warp;
    const float* e1r = g_e1 + (size_t)row*NEC;
    float r[16];
    #pragma unroll
    for (int k = 0; k < 16; k++) r[k] = e1r[lane + k*32];
    int b = row >> 11, v = row & (NV-1);
    #pragma unroll
    for (int o = 0; o < NOUT; o++) {
        float s = 0.f;
        #pragma unroll
        for (int k = 0; k < 16; k++) s += r[k]*w[o*NEC + lane + k*32];
        #pragma unroll
        for (int off = 16; off; off >>= 1) s += __shfl_xor_sync(0xffffffffu, s, off);
        if (lane == 0) out[((size_t)b*NOUT + o)*NV + v] = s + sb[o];
    }
}

// ---------------- launch ----------------
extern "C" void kernel_launch(void* const* d_in, const int* in_sizes, int n_in,
                              void* d_out, int out_size)
{
    (void)in_sizes; (void)n_in; (void)out_size;
    const float* x    = (const float*)d_in[0];
    const float* A    = (const float*)d_in[1];
    const float* nv1  = (const float*)d_in[2];
    const float* nv2  = (const float*)d_in[3];
    const float* fw   = (const float*)d_in[4];
    const float* fb   = (const float*)d_in[5];
    const float* gw   = (const float*)d_in[6];
    const float* gb   = (const float*)d_in[7];
    const float* sw   = (const float*)d_in[8];
    const float* sb   = (const float*)d_in[9];
    const float* gcnw = (const float*)d_in[10];
    const float* gcnb = (const float*)d_in[11];
    const float* bng  = (const float*)d_in[12];
    const float* bnb  = (const float*)d_in[13];
    const float* bnm  = (const float*)d_in[14];
    const float* bnv  = (const float*)d_in[15];
    const float* stw  = (const float*)d_in[16];
    const float* stb  = (const float*)d_in[17];
    const float* e1w  = (const float*)d_in[18];
    const float* e1b  = (const float*)d_in[19];
    const float* e2w  = (const float*)d_in[20];
    const float* e2b  = (const float*)d_in[21];

    __half *p_gx, *p_H, *p_skt, *p_w1r, *p_bt;
    float  *p_skip, *p_e1;
    cudaGetSymbolAddress((void**)&p_gx,   g_gx);
    cudaGetSymbolAddress((void**)&p_H,    g_H);
    cudaGetSymbolAddress((void**)&p_skip, g_skip);
    cudaGetSymbolAddress((void**)&p_skt,  g_skt);
    cudaGetSymbolAddress((void**)&p_e1,   g_e1);
    cudaGetSymbolAddress((void**)&p_w1r,  g_w1r);
    cudaGetSymbolAddress((void**)&p_bt,   g_bt);

    cudaFuncSetAttribute(mma_gemm, cudaFuncAttributeMaxDynamicSharedMemorySize, GSMEM);

    adp_kernel<<<NV, 256>>>(nv1, nv2);
    bt_kernel<<<dim3(NV/32, NV/32, 3), 256>>>(A);
    start_kernel<<<dim3(NV/256, 13, NB), 256>>>(x, stw, stb);
    cudaMemsetAsync(p_skip, 0, (size_t)NB*NSC*NV*sizeof(float));

    const int dil[NLAY] = {1,2,1,2,1,2,1,2};
    int Tin = 13, parity = 0;
    for (int i = 0; i < NLAY; i++) {
        int d = dil[i], Tout = Tin - d;
        gated_kernel<<<dim3(NV/256, Tout, NB), 256>>>(fw, fb, gw, gb, i, Tin, d, parity);
        skip_kernel<<<dim3(NV/256, NSC/8, NB), 256>>>(sw, sb, i, Tout);

        if (i < NLAY-1) {   // last layer's gcn output is dead code
            int M = NB*NRC*Tout;
            // hop 1: gx @ A_z -> H0, H2, H4
            mma_gemm<<<dim3(NV/BN, M/BM, 3), 256, GSMEM>>>(
                p_gx, p_bt, p_H,
                0L, (long)NN, 2L*HBUF,
                NV, NV, NV, NV/BK, nullptr, 4);
            // hop 2: H{0,2,4} @ A_z -> H1, H3, H5
            mma_gemm<<<dim3(NV/BN, M/BM, 3), 256, GSMEM>>>(
                p_H, p_bt, p_H + HBUF,
                2L*HBUF, (long)NN, 2L*HBUF,
                NV, NV, NV, NV/BK, nullptr, 4);
            gcn_kernel<<<dim3(NV/64, Tout, NB), 256>>>(gcnw, gcnb, bng, bnb, bnm, bnv,
                                                       i, Tin, d, parity);
        }
        parity ^= 1;
        Tin = Tout;
    }

    skt_kernel<<<dim3(NV/32, NSC/32, NB), 256>>>();
    w1r_kernel<<<(NEC*NSC)/256, 256>>>(e1w);
    mma_gemm<<<dim3(NEC/BN, (NB*NV)/BM, 1), 256, GSMEM>>>(
        p_skt, p_w1r, p_e1,
        0L, 0L, 0L,
        NSC, NSC, NEC, NSC/BK, e1b, 1);
    end2_kernel<<<(NB*NV)/8, 256>>>(e2w, e2b, (float*)d_out);
}

// round 9
// speedup vs baseline: 1.0998x; 1.0684x over previous
#include <cuda_runtime.h>
#include <cuda_fp16.h>
#include <math.h>
#include <stdint.h>

// ---------------- problem constants ----------------
#define NB   16
#define NV   2048
#define NRC  32
#define NSC  256
#define NEC  512
#define NOUT 12
#define NLAY 8
#define NN   (NV*NV)
#define XBUF (NB*NRC*13*NV)
#define HBUF (NB*NRC*12*NV)

// ---------------- device scratch ----------------
__device__ float  g_adp [NN];
__device__ __half g_bt  [3*NN];          // fp16 transposed supports [z][n][k]
__device__ float  g_xa  [XBUF];
__device__ float  g_xb  [XBUF];
__device__ __half g_gx  [HBUF];
__device__ __half g_H   [6*HBUF];
__device__ float  g_skip[NB*NSC*NV];
__device__ __half g_skt [NB*NV*NSC];
__device__ float  g_e1  [NB*NV*NEC];
__device__ __half g_w1r [NEC*NSC];       // fp16 e1w, already [n][k]
__device__ float  g_wgt [NLAY*224*32];   // gcn weights pre-transposed [l][gc][og*8+j]

// ---------------- helpers ----------------
__device__ __forceinline__ float tanh_fast(float x) {
    float y; asm("tanh.approx.f32 %0, %1;" : "=f"(y) : "f"(x));
    return y;
}
__device__ __forceinline__ uint32_t smem_u32(const void* p) {
    uint32_t a;
    asm("{ .reg .u64 t; cvta.to.shared.u64 t, %1; cvt.u32.u64 %0, t; }" : "=r"(a) : "l"(p));
    return a;
}
__device__ __forceinline__ void cp_async16(uint32_t dst, const void* src) {
    asm volatile("cp.async.cg.shared.global [%0], [%1], 16;" :: "r"(dst), "l"(src));
}
#define CP_COMMIT() asm volatile("cp.async.commit_group;" ::: "memory")

__device__ __forceinline__ void mma_f16_16x8x16(
    float& d0, float& d1, float& d2, float& d3,
    uint32_t a0, uint32_t a1, uint32_t a2, uint32_t a3,
    uint32_t b0, uint32_t b1)
{
    asm volatile(
        "mma.sync.aligned.m16n8k16.row.col.f32.f16.f16.f32 "
        "{%0,%1,%2,%3}, {%4,%5,%6,%7}, {%8,%9}, {%0,%1,%2,%3};"
        : "+f"(d0), "+f"(d1), "+f"(d2), "+f"(d3)
        : "r"(a0), "r"(a1), "r"(a2), "r"(a3), "r"(b0), "r"(b1));
}
__device__ __forceinline__ void ldsm_x4(
    uint32_t& r0, uint32_t& r1, uint32_t& r2, uint32_t& r3, uint32_t addr)
{
    asm volatile("ldmatrix.sync.aligned.m8n8.x4.shared.b16 {%0,%1,%2,%3}, [%4];"
        : "=r"(r0), "=r"(r1), "=r"(r2), "=r"(r3) : "r"(addr));
}

// ---------------- fp16 HMMA GEMM: C[M,N] = X[M,K] @ B[N,K]^T ----------------
// CTA tile 128x128, BK=64, 8 warps (4m x 2n), warp tile 32x64, 3-stage cp.async,
// ldmatrix fragment loads. Per-z strides: X += z*sX, B += z*sB, C += z*sC.
// flags: bit0 relu, bit2 fp16 out.
#define BM 128
#define BN 128
#define BK 64
#define KPAD_H 72
#define STG_H (BM*KPAD_H)
#define NSTAGE 3
#define GSMEM (NSTAGE*2*STG_H*2)

__global__ void __launch_bounds__(256) mma_gemm(
    const __half* __restrict__ X, const __half* __restrict__ B, void* __restrict__ Cv,
    long sX, long sB, long sC,
    int lda, int ldb, int ldc, int nkt,
    const float* __restrict__ bias, int flags)
{
    extern __shared__ __half sm[];

    int z = blockIdx.z;
    X += (size_t)z*sX;
    B += (size_t)z*sB;
    int m0 = blockIdx.y*BM, n0 = blockIdx.x*BN;

    int tid = threadIdx.x, wid = tid >> 5, lane = tid & 31;
    int wm = wid & 3, wn = wid >> 2;
    int lq = lane >> 2, lr = lane & 3;
    int lane15 = lane & 15, laneh = lane >> 4;

    uint32_t sbase = smem_u32(sm);

    auto load_stage = [&](int s, int k0) {
        uint32_t da = sbase + (uint32_t)(s*2*STG_H)*2;
        uint32_t db = da + (uint32_t)STG_H*2;
        const __half* xs = X + (size_t)m0*lda + k0;
        const __half* bs = B + (size_t)n0*ldb + k0;
        #pragma unroll
        for (int i = 0; i < 4; i++) {
            int l = tid + i*256;
            int row = l >> 3, seg = l & 7;
            uint32_t off = (uint32_t)(row*KPAD_H + seg*8)*2;
            cp_async16(da + off, xs + (size_t)row*lda + seg*8);
            cp_async16(db + off, bs + (size_t)row*ldb + seg*8);
        }
    };

    float acc[2][8][4];
    #pragma unroll
    for (int mt = 0; mt < 2; mt++)
        #pragma unroll
        for (int nt = 0; nt < 8; nt++)
            #pragma unroll
            for (int k = 0; k < 4; k++) acc[mt][nt][k] = 0.f;

    load_stage(0, 0);  CP_COMMIT();
    if (nkt > 1) load_stage(1, BK);
    CP_COMMIT();

    // per-lane ldmatrix base offsets (halves) within a slab
    // A tile mt: rows wm*32 + mt*16 + (lane&15), col 8*(lane>>4)
    uint32_t aoff0 = (uint32_t)((wm*32 + lane15)*KPAD_H + 8*laneh);
    uint32_t aoff1 = aoff0 + 16u*KPAD_H;
    // B pair nt2: rows wn*64 + nt2*16 + (lane&15)
    uint32_t boff  = (uint32_t)(STG_H + (wn*64 + lane15)*KPAD_H + 8*laneh);

    for (int kt = 0; kt < nkt; kt++) {
        asm volatile("cp.async.wait_group 1;" ::: "memory");
        __syncthreads();

        if (kt + 2 < nkt) load_stage((kt+2) % NSTAGE, (kt+2)*BK);
        CP_COMMIT();

        uint32_t slab = sbase + (uint32_t)((kt % NSTAGE)*2*STG_H)*2;

        uint32_t a[2][2][4], b[2][8][2];
        // prefetch k16 chunk 0
        ldsm_x4(a[0][0][0], a[0][0][1], a[0][0][2], a[0][0][3], slab + aoff0*2);
        ldsm_x4(a[0][1][0], a[0][1][1], a[0][1][2], a[0][1][3], slab + aoff1*2);
        #pragma unroll
        for (int nt2 = 0; nt2 < 4; nt2++) {
            uint32_t r0, r1, r2, r3;
            ldsm_x4(r0, r1, r2, r3, slab + (boff + nt2*16u*KPAD_H)*2);
            b[0][2*nt2][0] = r0; b[0][2*nt2+1][0] = r1;
            b[0][2*nt2][1] = r2; b[0][2*nt2+1][1] = r3;
        }

        #pragma unroll
        for (int k16 = 0; k16 < BK/16; k16++) {
            int cur = k16 & 1, nxt = cur ^ 1;
            if (k16 + 1 < BK/16) {
                uint32_t kk = (uint32_t)((k16 + 1)*16)*2;   // byte offset along K
                ldsm_x4(a[nxt][0][0], a[nxt][0][1], a[nxt][0][2], a[nxt][0][3],
                        slab + aoff0*2 + kk);
                ldsm_x4(a[nxt][1][0], a[nxt][1][1], a[nxt][1][2], a[nxt][1][3],
                        slab + aoff1*2 + kk);
                #pragma unroll
                for (int nt2 = 0; nt2 < 4; nt2++) {
                    uint32_t r0, r1, r2, r3;
                    ldsm_x4(r0, r1, r2, r3, slab + (boff + nt2*16u*KPAD_H)*2 + kk);
                    b[nxt][2*nt2][0] = r0; b[nxt][2*nt2+1][0] = r1;
                    b[nxt][2*nt2][1] = r2; b[nxt][2*nt2+1][1] = r3;
                }
            }
            #pragma unroll
            for (int mt = 0; mt < 2; mt++)
                #pragma unroll
                for (int nt = 0; nt < 8; nt++)
                    mma_f16_16x8x16(acc[mt][nt][0], acc[mt][nt][1], acc[mt][nt][2], acc[mt][nt][3],
                                    a[cur][mt][0], a[cur][mt][1], a[cur][mt][2], a[cur][mt][3],
                                    b[cur][nt][0], b[cur][nt][1]);
        }
    }

    int rowa = m0 + wm*32 + lq;
    int colb = n0 + wn*64 + 2*lr;
    if (flags & 4) {
        __half* Ch = (__half*)Cv + (size_t)z*sC;
        #pragma unroll
        for (int mt = 0; mt < 2; mt++) {
            #pragma unroll
            for (int nt = 0; nt < 8; nt++) {
                __half2 h0 = __floats2half2_rn(acc[mt][nt][0], acc[mt][nt][1]);
                __half2 h1 = __floats2half2_rn(acc[mt][nt][2], acc[mt][nt][3]);
                *(__half2*)(Ch + (size_t)(rowa + mt*16)*ldc + colb + nt*8) = h0;
                *(__half2*)(Ch + (size_t)(rowa + mt*16 + 8)*ldc + colb + nt*8) = h1;
            }
        }
    } else {
        float* Cf = (float*)Cv + (size_t)z*sC;
        #pragma unroll
        for (int mt = 0; mt < 2; mt++) {
            #pragma unroll
            for (int nt = 0; nt < 8; nt++) {
                float v0 = acc[mt][nt][0], v1 = acc[mt][nt][1];
                float v2 = acc[mt][nt][2], v3 = acc[mt][nt][3];
                if (bias) {
                    float b0 = bias[colb + nt*8], b1 = bias[colb + nt*8 + 1];
                    v0 += b0; v1 += b1; v2 += b0; v3 += b1;
                }
                if (flags & 1) {
                    v0 = fmaxf(v0, 0.f); v1 = fmaxf(v1, 0.f);
                    v2 = fmaxf(v2, 0.f); v3 = fmaxf(v3, 0.f);
                }
                float2 w0; w0.x = v0; w0.y = v1;
                float2 w1; w1.x = v2; w1.y = v3;
                *(float2*)(Cf + (size_t)(rowa + mt*16)*ldc + colb + nt*8) = w0;
                *(float2*)(Cf + (size_t)(rowa + mt*16 + 8)*ldc + colb + nt*8) = w1;
            }
        }
    }
}

// ---------------- adp = softmax(relu(nv1 @ nv2), axis=1) ----------------
__global__ void adp_kernel(const float* __restrict__ nv1, const float* __restrict__ nv2)
{
    int row = blockIdx.x;
    int tid = threadIdx.x;
    __shared__ float v1[10];
    __shared__ float red[256];
    if (tid < 10) v1[tid] = nv1[row*10 + tid];
    __syncthreads();
    float vals[8];
    float mx = -1e30f;
    #pragma unroll
    for (int j = 0; j < 8; j++) {
        int col = tid + j*256;
        float s = 0.f;
        #pragma unroll
        for (int k = 0; k < 10; k++) s += v1[k]*nv2[k*NV + col];
        s = fmaxf(s, 0.f);
        vals[j] = s;
        mx = fmaxf(mx, s);
    }
    red[tid] = mx; __syncthreads();
    for (int s2 = 128; s2 > 0; s2 >>= 1) {
        if (tid < s2) red[tid] = fmaxf(red[tid], red[tid+s2]);
        __syncthreads();
    }
    mx = red[0];
    __syncthreads();
    float sum = 0.f;
    #pragma unroll
    for (int j = 0; j < 8; j++) { vals[j] = expf(vals[j] - mx); sum += vals[j]; }
    red[tid] = sum; __syncthreads();
    for (int s2 = 128; s2 > 0; s2 >>= 1) {
        if (tid < s2) red[tid] += red[tid+s2];
        __syncthreads();
    }
    float inv = 1.f/red[0];
    #pragma unroll
    for (int j = 0; j < 8; j++) g_adp[row*NV + tid + j*256] = vals[j]*inv;
}

// ---------------- build fp16 transposed supports ----------------
__global__ void bt_kernel(const float* __restrict__ A)
{
    __shared__ float tile[32][33];
    int z = blockIdx.z;
    const float* S = (z < 2) ? (A + (size_t)z*NN) : g_adp;
    int r0 = blockIdx.y*32, c0 = blockIdx.x*32;
    int x = threadIdx.x & 31, y = threadIdx.x >> 5;
    #pragma unroll
    for (int i = 0; i < 32; i += 8)
        tile[y+i][x] = S[(size_t)(r0 + y + i)*NV + c0 + x];
    __syncthreads();
    #pragma unroll
    for (int i = 0; i < 32; i += 8)
        g_bt[((size_t)z*NV + c0 + y + i)*NV + r0 + x] = __float2half(tile[x][y+i]);
}

// ---------------- one-time gcn weight transpose: g_wgt[l][gc][og*8+j] ----------------
__global__ void gw_prep(const float* __restrict__ gw)
{
    int idx = blockIdx.x*256 + threadIdx.x;     // NLAY*224*32
    int l  = idx / (224*32);
    int r  = idx % (224*32);
    int gc = r >> 5, q = r & 31;
    int og2 = q >> 3, j = q & 7;
    g_wgt[idx] = gw[l*NRC*224 + (og2 + j*4)*224 + gc];
}

// ---------------- pad + start 1x1 conv ----------------
__global__ void start_kernel(const float* __restrict__ x,
                             const float* __restrict__ sw, const float* __restrict__ sb)
{
    int v = blockIdx.x*256 + threadIdx.x;
    int t = blockIdx.y, b = blockIdx.z;
    float in0 = 0.f, in1 = 0.f;
    if (t > 0) {
        in0 = x[((b*2+0)*NV + v)*12 + (t-1)];
        in1 = x[((b*2+1)*NV + v)*12 + (t-1)];
    }
    #pragma unroll
    for (int o = 0; o < NRC; o++) {
        g_xa[((b*NRC+o)*13 + t)*NV + v] = sb[o] + sw[o*2]*in0 + sw[o*2+1]*in1;
    }
}

// ---------------- gated dilated conv -> fp16 gx (packed float4 weights) ----------------
__global__ __launch_bounds__(256) void gated_kernel(
    const float* __restrict__ fw, const float* __restrict__ fb,
    const float* __restrict__ gw, const float* __restrict__ gb,
    int layer, int Tin, int d, int parity)
{
    const float* xin = parity ? g_xb : g_xa;
    int Tout = Tin - d;
    int v = blockIdx.x*256 + threadIdx.x;
    int t = blockIdx.y, b = blockIdx.z;

    __shared__ float4 swp[NRC*NRC];          // {fw0, fw1, gw0, gw1}
    __shared__ float sfb[NRC], sgb[NRC];
    const float* fwl = fw + layer*NRC*NRC*2;
    const float* gwl = gw + layer*NRC*NRC*2;
    for (int i = threadIdx.x; i < NRC*NRC; i += 256) {
        float2 fv = *(const float2*)(fwl + i*2);
        float2 gv = *(const float2*)(gwl + i*2);
        swp[i] = make_float4(fv.x, fv.y, gv.x, gv.y);
    }
    if (threadIdx.x < NRC) {
        sfb[threadIdx.x] = fb[layer*NRC + threadIdx.x];
        sgb[threadIdx.x] = gb[layer*NRC + threadIdx.x];
    }
    __syncthreads();

    float x0[NRC], x1[NRC];
    #pragma unroll
    for (int c = 0; c < NRC; c++) {
        x0[c] = xin[((b*NRC+c)*Tin + t    )*NV + v];
        x1[c] = xin[((b*NRC+c)*Tin + t + d)*NV + v];
    }
    #pragma unroll 4
    for (int o = 0; o < NRC; o++) {
        float f = sfb[o], g = sgb[o];
        #pragma unroll
        for (int c = 0; c < NRC; c++) {
            float4 w = swp[o*NRC + c];
            f += w.x*x0[c] + w.y*x1[c];
            g += w.z*x0[c] + w.w*x1[c];
        }
        float filt = tanh_fast(f);
        float gate = 0.5f*tanh_fast(0.5f*g) + 0.5f;
        g_gx[((b*NRC+o)*Tout + t)*NV + v] = __float2half(filt*gate);
    }
}

// ---------------- skip conv (last time step only) ----------------
__global__ __launch_bounds__(256) void skip_kernel(
    const float* __restrict__ sw, const float* __restrict__ sb, int layer, int Tout)
{
    int v  = blockIdx.x*256 + threadIdx.x;
    int og = blockIdx.y*8;
    int b  = blockIdx.z;
    const float* swl = sw + layer*NSC*NRC;
    const float* sbl = sb + layer*NSC;
    __shared__ float w[8][NRC];
    {
        int j = threadIdx.x / NRC, c = threadIdx.x % NRC;
        w[j][c] = swl[(og + j)*NRC + c];
    }
    __syncthreads();
    float acc[8];
    #pragma unroll
    for (int j = 0; j < 8; j++) acc[j] = sbl[og + j];
    #pragma unroll
    for (int c = 0; c < NRC; c++) {
        float gv = __half2float(g_gx[((b*NRC+c)*Tout + (Tout-1))*NV + v]);
        #pragma unroll
        for (int j = 0; j < 8; j++) acc[j] += w[j][c]*gv;
    }
    #pragma unroll
    for (int j = 0; j < 8; j++) g_skip[(b*NSC + og + j)*NV + v] += acc[j];
}

// ---------------- gcn 1x1 conv + bias + residual + BN ----------------
__global__ __launch_bounds__(256) void gcn_kernel(
    const float* __restrict__ gb,
    const float* __restrict__ bng, const float* __restrict__ bnb,
    const float* __restrict__ bnm, const float* __restrict__ bnv,
    int layer, int Tin, int d, int parity)
{
    int Tout = Tin - d;
    const float* xin  = parity ? g_xb : g_xa;
    float*       xout = parity ? g_xa : g_xb;

    __shared__ float ws[224*32];     // ws[gc][og*8 + j]
    __shared__ float hs[NRC][64];
    __shared__ float s_inv[NRC], s_beta[NRC], s_mean[NRC], s_gb[NRC];

    const float* wsrc = g_wgt + layer*224*32;
    for (int i = threadIdx.x; i < 224*32; i += 256) ws[i] = wsrc[i];
    if (threadIdx.x < NRC) {
        int o = threadIdx.x;
        s_inv [o] = bng[layer*NRC+o]*rsqrtf(bnv[layer*NRC+o] + 1e-5f);
        s_beta[o] = bnb[layer*NRC+o];
        s_mean[o] = bnm[layer*NRC+o];
        s_gb  [o] = gb [layer*NRC+o];
    }

    int vi = threadIdx.x & 63;
    int og = threadIdx.x >> 6;
    int v0 = blockIdx.x*64;
    int t = blockIdx.y, b = blockIdx.z;

    float acc[8];
    #pragma unroll
    for (int j = 0; j < 8; j++) acc[j] = 0.f;

    for (int g = 0; g < 7; g++) {
        const __half* H = (g == 0) ? g_gx : (g_H + (size_t)(g-1)*HBUF);
        __syncthreads();
        for (int i = threadIdx.x; i < NRC*64; i += 256) {
            int c = i >> 6, vv = i & 63;
            hs[c][vv] = __half2float(H[((b*NRC+c)*Tout + t)*NV + v0 + vv]);
        }
        __syncthreads();
        #pragma unroll
        for (int c = 0; c < 32; c++) {
            float hv = hs[c][vi];
            const float4* wp = (const float4*)&ws[(g*32 + c)*32 + og*8];
            float4 wa = wp[0], wb = wp[1];
            acc[0] += wa.x*hv; acc[1] += wa.y*hv; acc[2] += wa.z*hv; acc[3] += wa.w*hv;
            acc[4] += wb.x*hv; acc[5] += wb.y*hv; acc[6] += wb.z*hv; acc[7] += wb.w*hv;
        }
    }

    #pragma unroll
    for (int j = 0; j < 8; j++) {
        int o = og + j*4;
        float val = acc[j] + s_gb[o]
                  + xin[((b*NRC+o)*Tin + (t + d))*NV + v0 + vi];
        val = (val - s_mean[o])*s_inv[o] + s_beta[o];
        xout[((b*NRC+o)*Tout + t)*NV + v0 + vi] = val;
    }
}

// ---------------- relu + transpose skip -> fp16 [b*v][c] ----------------
__global__ void skt_kernel()
{
    __shared__ float tile[32][33];
    int b  = blockIdx.z;
    int c0 = blockIdx.y*32, v0 = blockIdx.x*32;
    int x = threadIdx.x % 32, y = threadIdx.x / 32;
    #pragma unroll
    for (int i = 0; i < 32; i += 8)
        tile[y+i][x] = g_skip[(b*NSC + c0 + y + i)*NV + v0 + x];
    __syncthreads();
    #pragma unroll
    for (int i = 0; i < 32; i += 8)
        g_skt[((size_t)b*NV + v0 + y + i)*NSC + c0 + x] = __float2half(fmaxf(tile[x][y+i], 0.f));
}

// ---------------- fp16 end1 weights ----------------
__global__ void w1r_kernel(const float* __restrict__ e1w)
{
    int idx = blockIdx.x*256 + threadIdx.x;
    g_w1r[idx] = __float2half(e1w[idx]);
}

// ---------------- end2 ----------------
__global__ __launch_bounds__(256) void end2_kernel(
    const float* __restrict__ e2w, const float* __restrict__ e2b, float* __restrict__ out)
{
    __shared__ float w[NOUT*NEC];
    __shared__ float sb[NOUT];
    for (int i = threadIdx.x; i < NOUT*NEC; i += 256) w[i] = e2w[i];
    if (threadIdx.x < NOUT) sb[threadIdx.x] = e2b[threadIdx.x];
    __syncthreads();

    int warp = threadIdx.x >> 5, lane = threadIdx.x & 31;
    int row = blockIdx.x*8 + warp;
    const float* e1r = g_e1 + (size_t)row*NEC;
    float r[16];
    #pragma unroll
    for (int k = 0; k < 16; k++) r[k] = e1r[lane + k*32];
    int b = row >> 11, v = row & (NV-1);
    #pragma unroll
    for (int o = 0; o < NOUT; o++) {
        float s = 0.f;
        #pragma unroll
        for (int k = 0; k < 16; k++) s += r[k]*w[o*NEC + lane + k*32];
        #pragma unroll
        for (int off = 16; off; off >>= 1) s += __shfl_xor_sync(0xffffffffu, s, off);
        if (lane == 0) out[((size_t)b*NOUT + o)*NV + v] = s + sb[o];
    }
}

// ---------------- launch ----------------
extern "C" void kernel_launch(void* const* d_in, const int* in_sizes, int n_in,
                              void* d_out, int out_size)
{
    (void)in_sizes; (void)n_in; (void)out_size;
    const float* x    = (const float*)d_in[0];
    const float* A    = (const float*)d_in[1];
    const float* nv1  = (const float*)d_in[2];
    const float* nv2  = (const float*)d_in[3];
    const float* fw   = (const float*)d_in[4];
    const float* fb   = (const float*)d_in[5];
    const float* gw   = (const float*)d_in[6];
    const float* gb   = (const float*)d_in[7];
    const float* sw   = (const float*)d_in[8];
    const float* sb   = (const float*)d_in[9];
    const float* gcnw = (const float*)d_in[10];
    const float* gcnb = (const float*)d_in[11];
    const float* bng  = (const float*)d_in[12];
    const float* bnb  = (const float*)d_in[13];
    const float* bnm  = (const float*)d_in[14];
    const float* bnv  = (const float*)d_in[15];
    const float* stw  = (const float*)d_in[16];
    const float* stb  = (const float*)d_in[17];
    const float* e1w  = (const float*)d_in[18];
    const float* e1b  = (const float*)d_in[19];
    const float* e2w  = (const float*)d_in[20];
    const float* e2b  = (const float*)d_in[21];

    __half *p_gx, *p_H, *p_skt, *p_w1r, *p_bt;
    float  *p_skip, *p_e1;
    cudaGetSymbolAddress((void**)&p_gx,   g_gx);
    cudaGetSymbolAddress((void**)&p_H,    g_H);
    cudaGetSymbolAddress((void**)&p_skip, g_skip);
    cudaGetSymbolAddress((void**)&p_skt,  g_skt);
    cudaGetSymbolAddress((void**)&p_e1,   g_e1);
    cudaGetSymbolAddress((void**)&p_w1r,  g_w1r);
    cudaGetSymbolAddress((void**)&p_bt,   g_bt);

    cudaFuncSetAttribute(mma_gemm, cudaFuncAttributeMaxDynamicSharedMemorySize, GSMEM);

    adp_kernel<<<NV, 256>>>(nv1, nv2);
    bt_kernel<<<dim3(NV/32, NV/32, 3), 256>>>(A);
    gw_prep<<<(NLAY*224*32)/256, 256>>>(gcnw);
    start_kernel<<<dim3(NV/256, 13, NB), 256>>>(x, stw, stb);
    cudaMemsetAsync(p_skip, 0, (size_t)NB*NSC*NV*sizeof(float));

    const int dil[NLAY] = {1,2,1,2,1,2,1,2};
    int Tin = 13, parity = 0;
    for (int i = 0; i < NLAY; i++) {
        int d = dil[i], Tout = Tin - d;
        gated_kernel<<<dim3(NV/256, Tout, NB), 256>>>(fw, fb, gw, gb, i, Tin, d, parity);
        skip_kernel<<<dim3(NV/256, NSC/8, NB), 256>>>(sw, sb, i, Tout);

        if (i < NLAY-1) {   // last layer's gcn output is dead code
            int M = NB*NRC*Tout;
            // hop 1: gx @ A_z -> H0, H2, H4
            mma_gemm<<<dim3(NV/BN, M/BM, 3), 256, GSMEM>>>(
                p_gx, p_bt, p_H,
                0L, (long)NN, 2L*HBUF,
                NV, NV, NV, NV/BK, nullptr, 4);
            // hop 2: H{0,2,4} @ A_z -> H1, H3, H5
            mma_gemm<<<dim3(NV/BN, M/BM, 3), 256, GSMEM>>>(
                p_H, p_bt, p_H + HBUF,
                2L*HBUF, (long)NN, 2L*HBUF,
                NV, NV, NV, NV/BK, nullptr, 4);
            gcn_kernel<<<dim3(NV/64, Tout, NB), 256>>>(gcnb, bng, bnb, bnm, bnv,
                                                       i, Tin, d, parity);
        }
        parity ^= 1;
        Tin = Tout;
    }

    skt_kernel<<<dim3(NV/32, NSC/32, NB), 256>>>();
    w1r_kernel<<<(NEC*NSC)/256, 256>>>(e1w);
    mma_gemm<<<dim3(NEC/BN, (NB*NV)/BM, 1), 256, GSMEM>>>(
        p_skt, p_w1r, p_e1,
        0L, 0L, 0L,
        NSC, NSC, NEC, NSC/BK, e1b, 1);
    end2_kernel<<<(NB*NV)/8, 256>>>(e2w, e2b, (float*)d_out);
}

// round 10
// speedup vs baseline: 1.1469x; 1.0428x over previous
#include <cuda_runtime.h>
#include <cuda_fp16.h>
#include <math.h>
#include <stdint.h>

// ---------------- problem constants ----------------
#define NB   16
#define NV   2048
#define NRC  32
#define NSC  256
#define NEC  512
#define NOUT 12
#define NLAY 8
#define NN   (NV*NV)
#define XBUF (NB*NRC*13*NV)
#define HBUF (NB*NRC*12*NV)

// ---------------- device scratch ----------------
__device__ float  g_adp [NN];
__device__ __half g_bt  [3*NN];          // fp16 transposed supports [z][n][k]
__device__ float  g_xa  [XBUF];
__device__ float  g_xb  [XBUF];
__device__ __half g_gx  [HBUF];
__device__ __half g_H   [6*HBUF];
__device__ __half g_gxl [NB*NV*NSC];     // last-timestep gated outs [bv][l*32+c]
__device__ __half g_wsk [NSC*NSC];       // stacked skip weights [j][l*32+c]
__device__ float  g_bsk [NSC];           // summed skip bias
__device__ __half g_skt [NB*NV*NSC];     // relu'd skip, [bv][j] fp16
__device__ float  g_e1  [NB*NV*NEC];
__device__ __half g_w1r [NEC*NSC];       // fp16 e1w, already [n][k]
__device__ float  g_wgt [NLAY*224*32];   // gcn weights pre-transposed [l][gc][og*8+j]

// ---------------- helpers ----------------
__device__ __forceinline__ float tanh_fast(float x) {
    float y; asm("tanh.approx.f32 %0, %1;" : "=f"(y) : "f"(x));
    return y;
}
__device__ __forceinline__ uint32_t smem_u32(const void* p) {
    uint32_t a;
    asm("{ .reg .u64 t; cvta.to.shared.u64 t, %1; cvt.u32.u64 %0, t; }" : "=r"(a) : "l"(p));
    return a;
}
__device__ __forceinline__ void cp_async16(uint32_t dst, const void* src) {
    asm volatile("cp.async.cg.shared.global [%0], [%1], 16;" :: "r"(dst), "l"(src));
}
#define CP_COMMIT() asm volatile("cp.async.commit_group;" ::: "memory")

__device__ __forceinline__ void mma_f16_16x8x16(
    float& d0, float& d1, float& d2, float& d3,
    uint32_t a0, uint32_t a1, uint32_t a2, uint32_t a3,
    uint32_t b0, uint32_t b1)
{
    asm volatile(
        "mma.sync.aligned.m16n8k16.row.col.f32.f16.f16.f32 "
        "{%0,%1,%2,%3}, {%4,%5,%6,%7}, {%8,%9}, {%0,%1,%2,%3};"
        : "+f"(d0), "+f"(d1), "+f"(d2), "+f"(d3)
        : "r"(a0), "r"(a1), "r"(a2), "r"(a3), "r"(b0), "r"(b1));
}
__device__ __forceinline__ void ldsm_x4(
    uint32_t& r0, uint32_t& r1, uint32_t& r2, uint32_t& r3, uint32_t addr)
{
    asm volatile("ldmatrix.sync.aligned.m8n8.x4.shared.b16 {%0,%1,%2,%3}, [%4];"
        : "=r"(r0), "=r"(r1), "=r"(r2), "=r"(r3) : "r"(addr));
}

// ---------------- fp16 HMMA GEMM: C[M,N] = X[M,K] @ B[N,K]^T ----------------
// CTA tile 128x128, BK=64, 8 warps (4m x 2n), warp tile 32x64, 3-stage cp.async,
// ldmatrix fragment loads. Per-z strides: X += z*sX, B += z*sB, C += z*sC.
// flags: bit0 relu, bit2 fp16 out. bias applies in both out modes.
#define BM 128
#define BN 128
#define BK 64
#define KPAD_H 72
#define STG_H (BM*KPAD_H)
#define NSTAGE 3
#define GSMEM (NSTAGE*2*STG_H*2)

__global__ void __launch_bounds__(256) mma_gemm(
    const __half* __restrict__ X, const __half* __restrict__ B, void* __restrict__ Cv,
    long sX, long sB, long sC,
    int lda, int ldb, int ldc, int nkt,
    const float* __restrict__ bias, int flags)
{
    extern __shared__ __half sm[];

    int z = blockIdx.z;
    X += (size_t)z*sX;
    B += (size_t)z*sB;
    int m0 = blockIdx.y*BM, n0 = blockIdx.x*BN;

    int tid = threadIdx.x, wid = tid >> 5, lane = tid & 31;
    int wm = wid & 3, wn = wid >> 2;
    int lq = lane >> 2, lr = lane & 3;
    int lane15 = lane & 15, laneh = lane >> 4;

    uint32_t sbase = smem_u32(sm);

    auto load_stage = [&](int s, int k0) {
        uint32_t da = sbase + (uint32_t)(s*2*STG_H)*2;
        uint32_t db = da + (uint32_t)STG_H*2;
        const __half* xs = X + (size_t)m0*lda + k0;
        const __half* bs = B + (size_t)n0*ldb + k0;
        #pragma unroll
        for (int i = 0; i < 4; i++) {
            int l = tid + i*256;
            int row = l >> 3, seg = l & 7;
            uint32_t off = (uint32_t)(row*KPAD_H + seg*8)*2;
            cp_async16(da + off, xs + (size_t)row*lda + seg*8);
            cp_async16(db + off, bs + (size_t)row*ldb + seg*8);
        }
    };

    float acc[2][8][4];
    #pragma unroll
    for (int mt = 0; mt < 2; mt++)
        #pragma unroll
        for (int nt = 0; nt < 8; nt++)
            #pragma unroll
            for (int k = 0; k < 4; k++) acc[mt][nt][k] = 0.f;

    load_stage(0, 0);  CP_COMMIT();
    if (nkt > 1) load_stage(1, BK);
    CP_COMMIT();

    uint32_t aoff0 = (uint32_t)((wm*32 + lane15)*KPAD_H + 8*laneh);
    uint32_t aoff1 = aoff0 + 16u*KPAD_H;
    uint32_t boff  = (uint32_t)(STG_H + (wn*64 + lane15)*KPAD_H + 8*laneh);

    for (int kt = 0; kt < nkt; kt++) {
        asm volatile("cp.async.wait_group 1;" ::: "memory");
        __syncthreads();

        if (kt + 2 < nkt) load_stage((kt+2) % NSTAGE, (kt+2)*BK);
        CP_COMMIT();

        uint32_t slab = sbase + (uint32_t)((kt % NSTAGE)*2*STG_H)*2;

        uint32_t a[2][2][4], b[2][8][2];
        ldsm_x4(a[0][0][0], a[0][0][1], a[0][0][2], a[0][0][3], slab + aoff0*2);
        ldsm_x4(a[0][1][0], a[0][1][1], a[0][1][2], a[0][1][3], slab + aoff1*2);
        #pragma unroll
        for (int nt2 = 0; nt2 < 4; nt2++) {
            uint32_t r0, r1, r2, r3;
            ldsm_x4(r0, r1, r2, r3, slab + (boff + nt2*16u*KPAD_H)*2);
            b[0][2*nt2][0] = r0; b[0][2*nt2+1][0] = r1;
            b[0][2*nt2][1] = r2; b[0][2*nt2+1][1] = r3;
        }

        #pragma unroll
        for (int k16 = 0; k16 < BK/16; k16++) {
            int cur = k16 & 1, nxt = cur ^ 1;
            if (k16 + 1 < BK/16) {
                uint32_t kk = (uint32_t)((k16 + 1)*16)*2;
                ldsm_x4(a[nxt][0][0], a[nxt][0][1], a[nxt][0][2], a[nxt][0][3],
                        slab + aoff0*2 + kk);
                ldsm_x4(a[nxt][1][0], a[nxt][1][1], a[nxt][1][2], a[nxt][1][3],
                        slab + aoff1*2 + kk);
                #pragma unroll
                for (int nt2 = 0; nt2 < 4; nt2++) {
                    uint32_t r0, r1, r2, r3;
                    ldsm_x4(r0, r1, r2, r3, slab + (boff + nt2*16u*KPAD_H)*2 + kk);
                    b[nxt][2*nt2][0] = r0; b[nxt][2*nt2+1][0] = r1;
                    b[nxt][2*nt2][1] = r2; b[nxt][2*nt2+1][1] = r3;
                }
            }
            #pragma unroll
            for (int mt = 0; mt < 2; mt++)
                #pragma unroll
                for (int nt = 0; nt < 8; nt++)
                    mma_f16_16x8x16(acc[mt][nt][0], acc[mt][nt][1], acc[mt][nt][2], acc[mt][nt][3],
                                    a[cur][mt][0], a[cur][mt][1], a[cur][mt][2], a[cur][mt][3],
                                    b[cur][nt][0], b[cur][nt][1]);
        }
    }

    int rowa = m0 + wm*32 + lq;
    int colb = n0 + wn*64 + 2*lr;
    #pragma unroll
    for (int mt = 0; mt < 2; mt++) {
        #pragma unroll
        for (int nt = 0; nt < 8; nt++) {
            float v0 = acc[mt][nt][0], v1 = acc[mt][nt][1];
            float v2 = acc[mt][nt][2], v3 = acc[mt][nt][3];
            if (bias) {
                float b0 = bias[colb + nt*8], b1 = bias[colb + nt*8 + 1];
                v0 += b0; v1 += b1; v2 += b0; v3 += b1;
            }
            if (flags & 1) {
                v0 = fmaxf(v0, 0.f); v1 = fmaxf(v1, 0.f);
                v2 = fmaxf(v2, 0.f); v3 = fmaxf(v3, 0.f);
            }
            if (flags & 4) {
                __half* Ch = (__half*)Cv + (size_t)z*sC;
                __half2 h0 = __floats2half2_rn(v0, v1);
                __half2 h1 = __floats2half2_rn(v2, v3);
                *(__half2*)(Ch + (size_t)(rowa + mt*16)*ldc + colb + nt*8) = h0;
                *(__half2*)(Ch + (size_t)(rowa + mt*16 + 8)*ldc + colb + nt*8) = h1;
            } else {
                float* Cf = (float*)Cv + (size_t)z*sC;
                float2 w0; w0.x = v0; w0.y = v1;
                float2 w1; w1.x = v2; w1.y = v3;
                *(float2*)(Cf + (size_t)(rowa + mt*16)*ldc + colb + nt*8) = w0;
                *(float2*)(Cf + (size_t)(rowa + mt*16 + 8)*ldc + colb + nt*8) = w1;
            }
        }
    }
}

// ---------------- adp = softmax(relu(nv1 @ nv2), axis=1) ----------------
__global__ void adp_kernel(const float* __restrict__ nv1, const float* __restrict__ nv2)
{
    int row = blockIdx.x;
    int tid = threadIdx.x;
    __shared__ float v1[10];
    __shared__ float red[256];
    if (tid < 10) v1[tid] = nv1[row*10 + tid];
    __syncthreads();
    float vals[8];
    float mx = -1e30f;
    #pragma unroll
    for (int j = 0; j < 8; j++) {
        int col = tid + j*256;
        float s = 0.f;
        #pragma unroll
        for (int k = 0; k < 10; k++) s += v1[k]*nv2[k*NV + col];
        s = fmaxf(s, 0.f);
        vals[j] = s;
        mx = fmaxf(mx, s);
    }
    red[tid] = mx; __syncthreads();
    for (int s2 = 128; s2 > 0; s2 >>= 1) {
        if (tid < s2) red[tid] = fmaxf(red[tid], red[tid+s2]);
        __syncthreads();
    }
    mx = red[0];
    __syncthreads();
    float sum = 0.f;
    #pragma unroll
    for (int j = 0; j < 8; j++) { vals[j] = expf(vals[j] - mx); sum += vals[j]; }
    red[tid] = sum; __syncthreads();
    for (int s2 = 128; s2 > 0; s2 >>= 1) {
        if (tid < s2) red[tid] += red[tid+s2];
        __syncthreads();
    }
    float inv = 1.f/red[0];
    #pragma unroll
    for (int j = 0; j < 8; j++) g_adp[row*NV + tid + j*256] = vals[j]*inv;
}

// ---------------- build fp16 transposed supports ----------------
__global__ void bt_kernel(const float* __restrict__ A)
{
    __shared__ float tile[32][33];
    int z = blockIdx.z;
    const float* S = (z < 2) ? (A + (size_t)z*NN) : g_adp;
    int r0 = blockIdx.y*32, c0 = blockIdx.x*32;
    int x = threadIdx.x & 31, y = threadIdx.x >> 5;
    #pragma unroll
    for (int i = 0; i < 32; i += 8)
        tile[y+i][x] = S[(size_t)(r0 + y + i)*NV + c0 + x];
    __syncthreads();
    #pragma unroll
    for (int i = 0; i < 32; i += 8)
        g_bt[((size_t)z*NV + c0 + y + i)*NV + r0 + x] = __float2half(tile[x][y+i]);
}

// ---------------- one-time gcn weight transpose ----------------
__global__ void gw_prep(const float* __restrict__ gw)
{
    int idx = blockIdx.x*256 + threadIdx.x;
    int l  = idx / (224*32);
    int r  = idx % (224*32);
    int gc = r >> 5, q = r & 31;
    int og2 = q >> 3, j = q & 7;
    g_wgt[idx] = gw[l*NRC*224 + (og2 + j*4)*224 + gc];
}

// ---------------- one-time skip weight stack + bias sum ----------------
__global__ void wsk_prep(const float* __restrict__ sw, const float* __restrict__ sb)
{
    int idx = blockIdx.x*256 + threadIdx.x;   // NSC*NSC = 65536
    int j = idx >> 8, k = idx & 255;
    int l = k >> 5, c = k & 31;
    g_wsk[idx] = __float2half(sw[(l*NSC + j)*NRC + c]);
    if (idx < NSC) {
        float s = 0.f;
        #pragma unroll
        for (int ll = 0; ll < NLAY; ll++) s += sb[ll*NSC + idx];
        g_bsk[idx] = s;
    }
}

// ---------------- pad + start 1x1 conv ----------------
__global__ void start_kernel(const float* __restrict__ x,
                             const float* __restrict__ sw, const float* __restrict__ sb)
{
    int v = blockIdx.x*256 + threadIdx.x;
    int t = blockIdx.y, b = blockIdx.z;
    float in0 = 0.f, in1 = 0.f;
    if (t > 0) {
        in0 = x[((b*2+0)*NV + v)*12 + (t-1)];
        in1 = x[((b*2+1)*NV + v)*12 + (t-1)];
    }
    #pragma unroll
    for (int o = 0; o < NRC; o++) {
        g_xa[((b*NRC+o)*13 + t)*NV + v] = sb[o] + sw[o*2]*in0 + sw[o*2+1]*in1;
    }
}

// ---------------- gated dilated conv -> fp16 gx; captures last timestep to g_gxl ----------------
__global__ __launch_bounds__(256) void gated_kernel(
    const float* __restrict__ fw, const float* __restrict__ fb,
    const float* __restrict__ gw, const float* __restrict__ gb,
    int layer, int Tin, int d, int parity)
{
    const float* xin = parity ? g_xb : g_xa;
    int Tout = Tin - d;
    int v = blockIdx.x*256 + threadIdx.x;
    int t = blockIdx.y, b = blockIdx.z;

    __shared__ float4 swp[NRC*NRC];          // {fw0, fw1, gw0, gw1}
    __shared__ float sfb[NRC], sgb[NRC];
    const float* fwl = fw + layer*NRC*NRC*2;
    const float* gwl = gw + layer*NRC*NRC*2;
    for (int i = threadIdx.x; i < NRC*NRC; i += 256) {
        float2 fv = *(const float2*)(fwl + i*2);
        float2 gv = *(const float2*)(gwl + i*2);
        swp[i] = make_float4(fv.x, fv.y, gv.x, gv.y);
    }
    if (threadIdx.x < NRC) {
        sfb[threadIdx.x] = fb[layer*NRC + threadIdx.x];
        sgb[threadIdx.x] = gb[layer*NRC + threadIdx.x];
    }
    __syncthreads();

    float x0[NRC], x1[NRC];
    #pragma unroll
    for (int c = 0; c < NRC; c++) {
        x0[c] = xin[((b*NRC+c)*Tin + t    )*NV + v];
        x1[c] = xin[((b*NRC+c)*Tin + t + d)*NV + v];
    }
    __half hb[NRC];
    #pragma unroll 4
    for (int o = 0; o < NRC; o++) {
        float f = sfb[o], g = sgb[o];
        #pragma unroll
        for (int c = 0; c < NRC; c++) {
            float4 w = swp[o*NRC + c];
            f += w.x*x0[c] + w.y*x1[c];
            g += w.z*x0[c] + w.w*x1[c];
        }
        float filt = tanh_fast(f);
        float gate = 0.5f*tanh_fast(0.5f*g) + 0.5f;
        __half h = __float2half(filt*gate);
        hb[o] = h;
        g_gx[((b*NRC+o)*Tout + t)*NV + v] = h;
    }
    if (t == Tout - 1) {
        uint4* dst = (uint4*)(g_gxl + ((size_t)b*NV + v)*NSC + layer*NRC);
        const uint4* src = (const uint4*)hb;
        dst[0] = src[0]; dst[1] = src[1]; dst[2] = src[2]; dst[3] = src[3];
    }
}

// ---------------- gcn 1x1 conv + bias + residual + BN ----------------
__global__ __launch_bounds__(256) void gcn_kernel(
    const float* __restrict__ gb,
    const float* __restrict__ bng, const float* __restrict__ bnb,
    const float* __restrict__ bnm, const float* __restrict__ bnv,
    int layer, int Tin, int d, int parity)
{
    int Tout = Tin - d;
    const float* xin  = parity ? g_xb : g_xa;
    float*       xout = parity ? g_xa : g_xb;

    __shared__ float ws[224*32];
    __shared__ float hs[NRC][64];
    __shared__ float s_inv[NRC], s_beta[NRC], s_mean[NRC], s_gb[NRC];

    const float* wsrc = g_wgt + layer*224*32;
    for (int i = threadIdx.x; i < 224*32; i += 256) ws[i] = wsrc[i];
    if (threadIdx.x < NRC) {
        int o = threadIdx.x;
        s_inv [o] = bng[layer*NRC+o]*rsqrtf(bnv[layer*NRC+o] + 1e-5f);
        s_beta[o] = bnb[layer*NRC+o];
        s_mean[o] = bnm[layer*NRC+o];
        s_gb  [o] = gb [layer*NRC+o];
    }

    int vi = threadIdx.x & 63;
    int og = threadIdx.x >> 6;
    int v0 = blockIdx.x*64;
    int t = blockIdx.y, b = blockIdx.z;

    float acc[8];
    #pragma unroll
    for (int j = 0; j < 8; j++) acc[j] = 0.f;

    for (int g = 0; g < 7; g++) {
        const __half* H = (g == 0) ? g_gx : (g_H + (size_t)(g-1)*HBUF);
        __syncthreads();
        for (int i = threadIdx.x; i < NRC*64; i += 256) {
            int c = i >> 6, vv = i & 63;
            hs[c][vv] = __half2float(H[((b*NRC+c)*Tout + t)*NV + v0 + vv]);
        }
        __syncthreads();
        #pragma unroll
        for (int c = 0; c < 32; c++) {
            float hv = hs[c][vi];
            const float4* wp = (const float4*)&ws[(g*32 + c)*32 + og*8];
            float4 wa = wp[0], wb = wp[1];
            acc[0] += wa.x*hv; acc[1] += wa.y*hv; acc[2] += wa.z*hv; acc[3] += wa.w*hv;
            acc[4] += wb.x*hv; acc[5] += wb.y*hv; acc[6] += wb.z*hv; acc[7] += wb.w*hv;
        }
    }

    #pragma unroll
    for (int j = 0; j < 8; j++) {
        int o = og + j*4;
        float val = acc[j] + s_gb[o]
                  + xin[((b*NRC+o)*Tin + (t + d))*NV + v0 + vi];
        val = (val - s_mean[o])*s_inv[o] + s_beta[o];
        xout[((b*NRC+o)*Tout + t)*NV + v0 + vi] = val;
    }
}

// ---------------- fp16 end1 weights ----------------
__global__ void w1r_kernel(const float* __restrict__ e1w)
{
    int idx = blockIdx.x*256 + threadIdx.x;
    g_w1r[idx] = __float2half(e1w[idx]);
}

// ---------------- end2 ----------------
__global__ __launch_bounds__(256) void end2_kernel(
    const float* __restrict__ e2w, const float* __restrict__ e2b, float* __restrict__ out)
{
    __shared__ float w[NOUT*NEC];
    __shared__ float sb[NOUT];
    for (int i = threadIdx.x; i < NOUT*NEC; i += 256) w[i] = e2w[i];
    if (threadIdx.x < NOUT) sb[threadIdx.x] = e2b[threadIdx.x];
    __syncthreads();

    int warp = threadIdx.x >> 5, lane = threadIdx.x & 31;
    int row = blockIdx.x*8 + warp;
    const float* e1r = g_e1 + (size_t)row*NEC;
    float r[16];
    #pragma unroll
    for (int k = 0; k < 16; k++) r[k] = e1r[lane + k*32];
    int b = row >> 11, v = row & (NV-1);
    #pragma unroll
    for (int o = 0; o < NOUT; o++) {
        float s = 0.f;
        #pragma unroll
        for (int k = 0; k < 16; k++) s += r[k]*w[o*NEC + lane + k*32];
        #pragma unroll
        for (int off = 16; off; off >>= 1) s += __shfl_xor_sync(0xffffffffu, s, off);
        if (lane == 0) out[((size_t)b*NOUT + o)*NV + v] = s + sb[o];
    }
}

// ---------------- launch ----------------
extern "C" void kernel_launch(void* const* d_in, const int* in_sizes, int n_in,
                              void* d_out, int out_size)
{
    (void)in_sizes; (void)n_in; (void)out_size;
    const float* x    = (const float*)d_in[0];
    const float* A    = (const float*)d_in[1];
    const float* nv1  = (const float*)d_in[2];
    const float* nv2  = (const float*)d_in[3];
    const float* fw   = (const float*)d_in[4];
    const float* fb   = (const float*)d_in[5];
    const float* gw   = (const float*)d_in[6];
    const float* gb   = (const float*)d_in[7];
    const float* sw   = (const float*)d_in[8];
    const float* sb   = (const float*)d_in[9];
    const float* gcnw = (const float*)d_in[10];
    const float* gcnb = (const float*)d_in[11];
    const float* bng  = (const float*)d_in[12];
    const float* bnb  = (const float*)d_in[13];
    const float* bnm  = (const float*)d_in[14];
    const float* bnv  = (const float*)d_in[15];
    const float* stw  = (const float*)d_in[16];
    const float* stb  = (const float*)d_in[17];
    const float* e1w  = (const float*)d_in[18];
    const float* e1b  = (const float*)d_in[19];
    const float* e2w  = (const float*)d_in[20];
    const float* e2b  = (const float*)d_in[21];

    __half *p_gx, *p_H, *p_skt, *p_w1r, *p_bt, *p_gxl, *p_wsk;
    float  *p_e1, *p_bsk;
    cudaGetSymbolAddress((void**)&p_gx,   g_gx);
    cudaGetSymbolAddress((void**)&p_H,    g_H);
    cudaGetSymbolAddress((void**)&p_skt,  g_skt);
    cudaGetSymbolAddress((void**)&p_e1,   g_e1);
    cudaGetSymbolAddress((void**)&p_w1r,  g_w1r);
    cudaGetSymbolAddress((void**)&p_bt,   g_bt);
    cudaGetSymbolAddress((void**)&p_gxl,  g_gxl);
    cudaGetSymbolAddress((void**)&p_wsk,  g_wsk);
    cudaGetSymbolAddress((void**)&p_bsk,  g_bsk);

    cudaFuncSetAttribute(mma_gemm, cudaFuncAttributeMaxDynamicSharedMemorySize, GSMEM);

    adp_kernel<<<NV, 256>>>(nv1, nv2);
    bt_kernel<<<dim3(NV/32, NV/32, 3), 256>>>(A);
    gw_prep<<<(NLAY*224*32)/256, 256>>>(gcnw);
    wsk_prep<<<(NSC*NSC)/256, 256>>>(sw, sb);
    start_kernel<<<dim3(NV/256, 13, NB), 256>>>(x, stw, stb);

    const int dil[NLAY] = {1,2,1,2,1,2,1,2};
    int Tin = 13, parity = 0;
    for (int i = 0; i < NLAY; i++) {
        int d = dil[i], Tout = Tin - d;
        gated_kernel<<<dim3(NV/256, Tout, NB), 256>>>(fw, fb, gw, gb, i, Tin, d, parity);

        if (i < NLAY-1) {   // last layer's gcn output is dead code
            int M = NB*NRC*Tout;
            // hop 1: gx @ A_z -> H0, H2, H4
            mma_gemm<<<dim3(NV/BN, M/BM, 3), 256, GSMEM>>>(
                p_gx, p_bt, p_H,
                0L, (long)NN, 2L*HBUF,
                NV, NV, NV, NV/BK, nullptr, 4);
            // hop 2: H{0,2,4} @ A_z -> H1, H3, H5
            mma_gemm<<<dim3(NV/BN, M/BM, 3), 256, GSMEM>>>(
                p_H, p_bt, p_H + HBUF,
                2L*HBUF, (long)NN, 2L*HBUF,
                NV, NV, NV, NV/BK, nullptr, 4);
            gcn_kernel<<<dim3(NV/64, Tout, NB), 256>>>(gcnb, bng, bnb, bnm, bnv,
                                                       i, Tin, d, parity);
        }
        parity ^= 1;
        Tin = Tout;
    }

    // skt[bv][j] = relu(gxl[bv][:] . wsk[j][:] + bsk[j])  (fp16 out)
    mma_gemm<<<dim3(NSC/BN, (NB*NV)/BM, 1), 256, GSMEM>>>(
        p_gxl, p_wsk, p_skt,
        0L, 0L, 0L,
        NSC, NSC, NSC, NSC/BK, p_bsk, 1|4);
    w1r_kernel<<<(NEC*NSC)/256, 256>>>(e1w);
    // E1 = relu(skt @ e1w^T + b1)
    mma_gemm<<<dim3(NEC/BN, (NB*NV)/BM, 1), 256, GSMEM>>>(
        p_skt, p_w1r, p_e1,
        0L, 0L, 0L,
        NSC, NSC, NEC, NSC/BK, e1b, 1);
    end2_kernel<<<(NB*NV)/8, 256>>>(e2w, e2b, (float*)d_out);
}

// round 11
// speedup vs baseline: 1.2190x; 1.0628x over previous
#include <cuda_runtime.h>
#include <cuda_fp16.h>
#include <math.h>
#include <stdint.h>

// ---------------- problem constants ----------------
#define NB   16
#define NV   2048
#define NRC  32
#define NSC  256
#define NEC  512
#define NOUT 12
#define NLAY 8
#define NN   (NV*NV)
#define XBUF (NB*NRC*13*NV)
#define HBUF (NB*NRC*12*NV)

// ---------------- device scratch ----------------
__device__ float  g_adp [NN];
__device__ __half g_bt  [3*NN];          // fp16 transposed supports [z][n][k]
__device__ float  g_xa  [XBUF];
__device__ float  g_xb  [XBUF];
__device__ __half g_gx  [HBUF];
__device__ __half g_H   [6*HBUF];
__device__ __half g_gxl [NB*NV*NSC];     // last-timestep gated outs [bv][l*32+c]
__device__ __half g_wsk [NSC*NSC];       // stacked skip weights [j][l*32+c]
__device__ float  g_bsk [NSC];           // summed skip bias
__device__ __half g_skt [NB*NV*NSC];     // relu'd skip, [bv][j] fp16
__device__ float  g_e1  [NB*NV*NEC];
__device__ __half g_w1r [NEC*NSC];       // fp16 e1w, already [n][k]
__device__ float  g_wgt [NLAY*224*32];   // gcn weights pre-transposed [l][gc][og*8+j]
__device__ __half g_wf  [NLAY*64*64];    // gated weights [l][q=2o+isg][k=2c+tap]

// ---------------- helpers ----------------
__device__ __forceinline__ float tanh_fast(float x) {
    float y; asm("tanh.approx.f32 %0, %1;" : "=f"(y) : "f"(x));
    return y;
}
__device__ __forceinline__ uint32_t smem_u32(const void* p) {
    uint32_t a;
    asm("{ .reg .u64 t; cvta.to.shared.u64 t, %1; cvt.u32.u64 %0, t; }" : "=r"(a) : "l"(p));
    return a;
}
__device__ __forceinline__ void cp_async16(uint32_t dst, const void* src) {
    asm volatile("cp.async.cg.shared.global [%0], [%1], 16;" :: "r"(dst), "l"(src));
}
#define CP_COMMIT() asm volatile("cp.async.commit_group;" ::: "memory")

__device__ __forceinline__ void mma_f16_16x8x16(
    float& d0, float& d1, float& d2, float& d3,
    uint32_t a0, uint32_t a1, uint32_t a2, uint32_t a3,
    uint32_t b0, uint32_t b1)
{
    asm volatile(
        "mma.sync.aligned.m16n8k16.row.col.f32.f16.f16.f32 "
        "{%0,%1,%2,%3}, {%4,%5,%6,%7}, {%8,%9}, {%0,%1,%2,%3};"
        : "+f"(d0), "+f"(d1), "+f"(d2), "+f"(d3)
        : "r"(a0), "r"(a1), "r"(a2), "r"(a3), "r"(b0), "r"(b1));
}
__device__ __forceinline__ void ldsm_x4(
    uint32_t& r0, uint32_t& r1, uint32_t& r2, uint32_t& r3, uint32_t addr)
{
    asm volatile("ldmatrix.sync.aligned.m8n8.x4.shared.b16 {%0,%1,%2,%3}, [%4];"
        : "=r"(r0), "=r"(r1), "=r"(r2), "=r"(r3) : "r"(addr));
}

// ---------------- fp16 HMMA GEMM: C[M,N] = X[M,K] @ B[N,K]^T ----------------
#define BM 128
#define BN 128
#define BK 64
#define KPAD_H 72
#define STG_H (BM*KPAD_H)
#define NSTAGE 3
#define GSMEM (NSTAGE*2*STG_H*2)

__global__ void __launch_bounds__(256) mma_gemm(
    const __half* __restrict__ X, const __half* __restrict__ B, void* __restrict__ Cv,
    long sX, long sB, long sC,
    int lda, int ldb, int ldc, int nkt,
    const float* __restrict__ bias, int flags)
{
    extern __shared__ __half sm[];

    int z = blockIdx.z;
    X += (size_t)z*sX;
    B += (size_t)z*sB;
    int m0 = blockIdx.y*BM, n0 = blockIdx.x*BN;

    int tid = threadIdx.x, wid = tid >> 5, lane = tid & 31;
    int wm = wid & 3, wn = wid >> 2;
    int lq = lane >> 2, lr = lane & 3;
    int lane15 = lane & 15, laneh = lane >> 4;

    uint32_t sbase = smem_u32(sm);

    auto load_stage = [&](int s, int k0) {
        uint32_t da = sbase + (uint32_t)(s*2*STG_H)*2;
        uint32_t db = da + (uint32_t)STG_H*2;
        const __half* xs = X + (size_t)m0*lda + k0;
        const __half* bs = B + (size_t)n0*ldb + k0;
        #pragma unroll
        for (int i = 0; i < 4; i++) {
            int l = tid + i*256;
            int row = l >> 3, seg = l & 7;
            uint32_t off = (uint32_t)(row*KPAD_H + seg*8)*2;
            cp_async16(da + off, xs + (size_t)row*lda + seg*8);
            cp_async16(db + off, bs + (size_t)row*ldb + seg*8);
        }
    };

    float acc[2][8][4];
    #pragma unroll
    for (int mt = 0; mt < 2; mt++)
        #pragma unroll
        for (int nt = 0; nt < 8; nt++)
            #pragma unroll
            for (int k = 0; k < 4; k++) acc[mt][nt][k] = 0.f;

    load_stage(0, 0);  CP_COMMIT();
    if (nkt > 1) load_stage(1, BK);
    CP_COMMIT();

    uint32_t aoff0 = (uint32_t)((wm*32 + lane15)*KPAD_H + 8*laneh);
    uint32_t aoff1 = aoff0 + 16u*KPAD_H;
    uint32_t boff  = (uint32_t)(STG_H + (wn*64 + lane15)*KPAD_H + 8*laneh);

    for (int kt = 0; kt < nkt; kt++) {
        asm volatile("cp.async.wait_group 1;" ::: "memory");
        __syncthreads();

        if (kt + 2 < nkt) load_stage((kt+2) % NSTAGE, (kt+2)*BK);
        CP_COMMIT();

        uint32_t slab = sbase + (uint32_t)((kt % NSTAGE)*2*STG_H)*2;

        uint32_t a[2][2][4], b[2][8][2];
        ldsm_x4(a[0][0][0], a[0][0][1], a[0][0][2], a[0][0][3], slab + aoff0*2);
        ldsm_x4(a[0][1][0], a[0][1][1], a[0][1][2], a[0][1][3], slab + aoff1*2);
        #pragma unroll
        for (int nt2 = 0; nt2 < 4; nt2++) {
            uint32_t r0, r1, r2, r3;
            ldsm_x4(r0, r1, r2, r3, slab + (boff + nt2*16u*KPAD_H)*2);
            b[0][2*nt2][0] = r0; b[0][2*nt2+1][0] = r1;
            b[0][2*nt2][1] = r2; b[0][2*nt2+1][1] = r3;
        }

        #pragma unroll
        for (int k16 = 0; k16 < BK/16; k16++) {
            int cur = k16 & 1, nxt = cur ^ 1;
            if (k16 + 1 < BK/16) {
                uint32_t kk = (uint32_t)((k16 + 1)*16)*2;
                ldsm_x4(a[nxt][0][0], a[nxt][0][1], a[nxt][0][2], a[nxt][0][3],
                        slab + aoff0*2 + kk);
                ldsm_x4(a[nxt][1][0], a[nxt][1][1], a[nxt][1][2], a[nxt][1][3],
                        slab + aoff1*2 + kk);
                #pragma unroll
                for (int nt2 = 0; nt2 < 4; nt2++) {
                    uint32_t r0, r1, r2, r3;
                    ldsm_x4(r0, r1, r2, r3, slab + (boff + nt2*16u*KPAD_H)*2 + kk);
                    b[nxt][2*nt2][0] = r0; b[nxt][2*nt2+1][0] = r1;
                    b[nxt][2*nt2][1] = r2; b[nxt][2*nt2+1][1] = r3;
                }
            }
            #pragma unroll
            for (int mt = 0; mt < 2; mt++)
                #pragma unroll
                for (int nt = 0; nt < 8; nt++)
                    mma_f16_16x8x16(acc[mt][nt][0], acc[mt][nt][1], acc[mt][nt][2], acc[mt][nt][3],
                                    a[cur][mt][0], a[cur][mt][1], a[cur][mt][2], a[cur][mt][3],
                                    b[cur][nt][0], b[cur][nt][1]);
        }
    }

    int rowa = m0 + wm*32 + lq;
    int colb = n0 + wn*64 + 2*lr;
    #pragma unroll
    for (int mt = 0; mt < 2; mt++) {
        #pragma unroll
        for (int nt = 0; nt < 8; nt++) {
            float v0 = acc[mt][nt][0], v1 = acc[mt][nt][1];
            float v2 = acc[mt][nt][2], v3 = acc[mt][nt][3];
            if (bias) {
                float b0 = bias[colb + nt*8], b1 = bias[colb + nt*8 + 1];
                v0 += b0; v1 += b1; v2 += b0; v3 += b1;
            }
            if (flags & 1) {
                v0 = fmaxf(v0, 0.f); v1 = fmaxf(v1, 0.f);
                v2 = fmaxf(v2, 0.f); v3 = fmaxf(v3, 0.f);
            }
            if (flags & 4) {
                __half* Ch = (__half*)Cv + (size_t)z*sC;
                __half2 h0 = __floats2half2_rn(v0, v1);
                __half2 h1 = __floats2half2_rn(v2, v3);
                *(__half2*)(Ch + (size_t)(rowa + mt*16)*ldc + colb + nt*8) = h0;
                *(__half2*)(Ch + (size_t)(rowa + mt*16 + 8)*ldc + colb + nt*8) = h1;
            } else {
                float* Cf = (float*)Cv + (size_t)z*sC;
                float2 w0; w0.x = v0; w0.y = v1;
                float2 w1; w1.x = v2; w1.y = v3;
                *(float2*)(Cf + (size_t)(rowa + mt*16)*ldc + colb + nt*8) = w0;
                *(float2*)(Cf + (size_t)(rowa + mt*16 + 8)*ldc + colb + nt*8) = w1;
            }
        }
    }
}

// ---------------- adp = softmax(relu(nv1 @ nv2), axis=1) ----------------
__global__ void adp_kernel(const float* __restrict__ nv1, const float* __restrict__ nv2)
{
    int row = blockIdx.x;
    int tid = threadIdx.x;
    __shared__ float v1[10];
    __shared__ float red[256];
    if (tid < 10) v1[tid] = nv1[row*10 + tid];
    __syncthreads();
    float vals[8];
    float mx = -1e30f;
    #pragma unroll
    for (int j = 0; j < 8; j++) {
        int col = tid + j*256;
        float s = 0.f;
        #pragma unroll
        for (int k = 0; k < 10; k++) s += v1[k]*nv2[k*NV + col];
        s = fmaxf(s, 0.f);
        vals[j] = s;
        mx = fmaxf(mx, s);
    }
    red[tid] = mx; __syncthreads();
    for (int s2 = 128; s2 > 0; s2 >>= 1) {
        if (tid < s2) red[tid] = fmaxf(red[tid], red[tid+s2]);
        __syncthreads();
    }
    mx = red[0];
    __syncthreads();
    float sum = 0.f;
    #pragma unroll
    for (int j = 0; j < 8; j++) { vals[j] = expf(vals[j] - mx); sum += vals[j]; }
    red[tid] = sum; __syncthreads();
    for (int s2 = 128; s2 > 0; s2 >>= 1) {
        if (tid < s2) red[tid] += red[tid+s2];
        __syncthreads();
    }
    float inv = 1.f/red[0];
    #pragma unroll
    for (int j = 0; j < 8; j++) g_adp[row*NV + tid + j*256] = vals[j]*inv;
}

// ---------------- build fp16 transposed supports ----------------
__global__ void bt_kernel(const float* __restrict__ A)
{
    __shared__ float tile[32][33];
    int z = blockIdx.z;
    const float* S = (z < 2) ? (A + (size_t)z*NN) : g_adp;
    int r0 = blockIdx.y*32, c0 = blockIdx.x*32;
    int x = threadIdx.x & 31, y = threadIdx.x >> 5;
    #pragma unroll
    for (int i = 0; i < 32; i += 8)
        tile[y+i][x] = S[(size_t)(r0 + y + i)*NV + c0 + x];
    __syncthreads();
    #pragma unroll
    for (int i = 0; i < 32; i += 8)
        g_bt[((size_t)z*NV + c0 + y + i)*NV + r0 + x] = __float2half(tile[x][y+i]);
}

// ---------------- one-time gcn weight transpose ----------------
__global__ void gw_prep(const float* __restrict__ gw)
{
    int idx = blockIdx.x*256 + threadIdx.x;
    int l  = idx / (224*32);
    int r  = idx % (224*32);
    int gc = r >> 5, q = r & 31;
    int og2 = q >> 3, j = q & 7;
    g_wgt[idx] = gw[l*NRC*224 + (og2 + j*4)*224 + gc];
}

// ---------------- one-time skip weight stack + bias sum ----------------
__global__ void wsk_prep(const float* __restrict__ sw, const float* __restrict__ sb)
{
    int idx = blockIdx.x*256 + threadIdx.x;
    int j = idx >> 8, k = idx & 255;
    int l = k >> 5, c = k & 31;
    g_wsk[idx] = __float2half(sw[(l*NSC + j)*NRC + c]);
    if (idx < NSC) {
        float s = 0.f;
        #pragma unroll
        for (int ll = 0; ll < NLAY; ll++) s += sb[ll*NSC + idx];
        g_bsk[idx] = s;
    }
}

// ---------------- one-time gated weight pack: g_wf[l][2o+isg][2c+tap] fp16 ----------------
__global__ void wf_prep(const float* __restrict__ fw, const float* __restrict__ gw)
{
    int idx = blockIdx.x*256 + threadIdx.x;   // NLAY*64*64 = 32768
    int l = idx >> 12;
    int rem = idx & 4095;
    int q = rem >> 6, k = rem & 63;
    int o = q >> 1, isg = q & 1;
    int c = k >> 1, tap = k & 1;
    const float* W = isg ? gw : fw;
    g_wf[idx] = __float2half(W[((l*NRC + o)*NRC + c)*2 + tap]);
}

// ---------------- pad + start 1x1 conv ----------------
__global__ void start_kernel(const float* __restrict__ x,
                             const float* __restrict__ sw, const float* __restrict__ sb)
{
    int v = blockIdx.x*256 + threadIdx.x;
    int t = blockIdx.y, b = blockIdx.z;
    float in0 = 0.f, in1 = 0.f;
    if (t > 0) {
        in0 = x[((b*2+0)*NV + v)*12 + (t-1)];
        in1 = x[((b*2+1)*NV + v)*12 + (t-1)];
    }
    #pragma unroll
    for (int o = 0; o < NRC; o++) {
        g_xa[((b*NRC+o)*13 + t)*NV + v] = sb[o] + sw[o*2]*in0 + sw[o*2+1]*in1;
    }
}

// ---------------- gated dilated conv via HMMA ----------------
// Block = (v-tile 128, t, b). C[128v, 64q] = Xcat[128v,64k] @ Wf[64q,64k]^T,
// q=2o+isg interleaves filt/gate -> (c0,c1) is a (filt,gate) pair per lane.
#define GPAD 72
__global__ void __launch_bounds__(256) gated_mma(
    const float* __restrict__ fb, const float* __restrict__ gb,
    int layer, int Tin, int d, int parity)
{
    __shared__ __half Xs[128*GPAD];
    __shared__ __half Ws[64*GPAD];
    __shared__ __half Os[32*136];
    __shared__ float sfb[NRC], sgb[NRC];

    const float* xin = parity ? g_xb : g_xa;
    int Tout = Tin - d;
    int v0 = blockIdx.x*128;
    int t = blockIdx.y, b = blockIdx.z;
    int tid = threadIdx.x, wid = tid >> 5, lane = tid & 31;
    int lq = lane >> 2, lr = lane & 3;
    int lane15 = lane & 15, laneh = lane >> 4;

    // stage W [64q][64k]
    const __half* wsrc = g_wf + layer*64*64;
    for (int i = tid; i < 64*32; i += 256) {
        int row = i >> 5, col2 = (i & 31)*2;
        *(uint32_t*)&Ws[row*GPAD + col2] = *(const uint32_t*)&wsrc[row*64 + col2];
    }
    if (tid < NRC) {
        sfb[tid] = fb[layer*NRC + tid];
        sgb[tid] = gb[layer*NRC + tid];
    }
    // stage X: row r = 2c+tap -> Xs[v][r]
    {
        int v = tid & 127;
        #pragma unroll
        for (int i = 0; i < 32; i++) {
            int r = i*2 + (tid >> 7);
            int c = r >> 1, tap = r & 1;
            float val = xin[((b*NRC + c)*Tin + t + tap*d)*NV + v0 + v];
            Xs[v*GPAD + r] = __float2half(val);
        }
    }
    __syncthreads();

    uint32_t sx = smem_u32(Xs), sw_ = smem_u32(Ws);
    // warp wid owns m-tile rows v = wid*16..+15, all 8 n-tiles
    float acc[8][4];
    #pragma unroll
    for (int nt = 0; nt < 8; nt++)
        #pragma unroll
        for (int k = 0; k < 4; k++) acc[nt][k] = 0.f;

    uint32_t axa = sx + (uint32_t)((wid*16 + lane15)*GPAD + 8*laneh)*2;
    uint32_t bxa = sw_ + (uint32_t)(lane15*GPAD + 8*laneh)*2;

    #pragma unroll
    for (int k16 = 0; k16 < 4; k16++) {
        uint32_t kk = (uint32_t)(k16*16)*2;
        uint32_t a0, a1, a2, a3;
        ldsm_x4(a0, a1, a2, a3, axa + kk);
        uint32_t bfr[8][2];
        #pragma unroll
        for (int nt2 = 0; nt2 < 4; nt2++) {
            uint32_t r0, r1, r2, r3;
            ldsm_x4(r0, r1, r2, r3, bxa + (uint32_t)(nt2*16*GPAD)*2 + kk);
            bfr[2*nt2][0] = r0; bfr[2*nt2+1][0] = r1;
            bfr[2*nt2][1] = r2; bfr[2*nt2+1][1] = r3;
        }
        #pragma unroll
        for (int nt = 0; nt < 8; nt++)
            mma_f16_16x8x16(acc[nt][0], acc[nt][1], acc[nt][2], acc[nt][3],
                            a0, a1, a2, a3, bfr[nt][0], bfr[nt][1]);
    }

    // epilogue: activations into Os[o][v]
    #pragma unroll
    for (int nt = 0; nt < 8; nt++) {
        int o = nt*4 + lr;
        float fbv = sfb[o], gbv = sgb[o];
        float f0 = tanh_fast(acc[nt][0] + fbv);
        float g0 = 0.5f*tanh_fast(0.5f*(acc[nt][1] + gbv)) + 0.5f;
        float f1 = tanh_fast(acc[nt][2] + fbv);
        float g1 = 0.5f*tanh_fast(0.5f*(acc[nt][3] + gbv)) + 0.5f;
        Os[o*136 + wid*16 + lq]     = __float2half(f0*g0);
        Os[o*136 + wid*16 + lq + 8] = __float2half(f1*g1);
    }
    __syncthreads();

    // coalesced copy Os -> g_gx
    #pragma unroll
    for (int i = 0; i < 2; i++) {
        int idx = tid + i*256;           // 0..511 = 32 rows x 16 chunks
        int row = idx >> 4, ch = idx & 15;
        uint4 val = *(const uint4*)&Os[row*136 + ch*8];
        *(uint4*)&g_gx[((size_t)(b*NRC + row)*Tout + t)*NV + v0 + ch*8] = val;
    }
    // last-timestep capture -> g_gxl
    if (t == Tout - 1) {
        int v = tid >> 1, oh = tid & 1;
        __half hb[16];
        #pragma unroll
        for (int i = 0; i < 16; i++) hb[i] = Os[(oh*16 + i)*136 + v];
        uint4* dst = (uint4*)(g_gxl + ((size_t)b*NV + v0 + v)*NSC + layer*NRC + oh*16);
        const uint4* src = (const uint4*)hb;
        dst[0] = src[0]; dst[1] = src[1];
    }
}

// ---------------- gcn 1x1 conv + bias + residual + BN ----------------
__global__ __launch_bounds__(256) void gcn_kernel(
    const float* __restrict__ gb,
    const float* __restrict__ bng, const float* __restrict__ bnb,
    const float* __restrict__ bnm, const float* __restrict__ bnv,
    int layer, int Tin, int d, int parity)
{
    int Tout = Tin - d;
    const float* xin  = parity ? g_xb : g_xa;
    float*       xout = parity ? g_xa : g_xb;

    __shared__ float ws[224*32];
    __shared__ float hs[NRC][64];
    __shared__ float s_inv[NRC], s_beta[NRC], s_mean[NRC], s_gb[NRC];

    const float* wsrc = g_wgt + layer*224*32;
    for (int i = threadIdx.x; i < 224*32; i += 256) ws[i] = wsrc[i];
    if (threadIdx.x < NRC) {
        int o = threadIdx.x;
        s_inv [o] = bng[layer*NRC+o]*rsqrtf(bnv[layer*NRC+o] + 1e-5f);
        s_beta[o] = bnb[layer*NRC+o];
        s_mean[o] = bnm[layer*NRC+o];
        s_gb  [o] = gb [layer*NRC+o];
    }

    int vi = threadIdx.x & 63;
    int og = threadIdx.x >> 6;
    int v0 = blockIdx.x*64;
    int t = blockIdx.y, b = blockIdx.z;

    float acc[8];
    #pragma unroll
    for (int j = 0; j < 8; j++) acc[j] = 0.f;

    for (int g = 0; g < 7; g++) {
        const __half* H = (g == 0) ? g_gx : (g_H + (size_t)(g-1)*HBUF);
        __syncthreads();
        for (int i = threadIdx.x; i < NRC*64; i += 256) {
            int c = i >> 6, vv = i & 63;
            hs[c][vv] = __half2float(H[((b*NRC+c)*Tout + t)*NV + v0 + vv]);
        }
        __syncthreads();
        #pragma unroll
        for (int c = 0; c < 32; c++) {
            float hv = hs[c][vi];
            const float4* wp = (const float4*)&ws[(g*32 + c)*32 + og*8];
            float4 wa = wp[0], wb = wp[1];
            acc[0] += wa.x*hv; acc[1] += wa.y*hv; acc[2] += wa.z*hv; acc[3] += wa.w*hv;
            acc[4] += wb.x*hv; acc[5] += wb.y*hv; acc[6] += wb.z*hv; acc[7] += wb.w*hv;
        }
    }

    #pragma unroll
    for (int j = 0; j < 8; j++) {
        int o = og + j*4;
        float val = acc[j] + s_gb[o]
                  + xin[((b*NRC+o)*Tin + (t + d))*NV + v0 + vi];
        val = (val - s_mean[o])*s_inv[o] + s_beta[o];
        xout[((b*NRC+o)*Tout + t)*NV + v0 + vi] = val;
    }
}

// ---------------- fp16 end1 weights ----------------
__global__ void w1r_kernel(const float* __restrict__ e1w)
{
    int idx = blockIdx.x*256 + threadIdx.x;
    g_w1r[idx] = __float2half(e1w[idx]);
}

// ---------------- end2 ----------------
__global__ __launch_bounds__(256) void end2_kernel(
    const float* __restrict__ e2w, const float* __restrict__ e2b, float* __restrict__ out)
{
    __shared__ float w[NOUT*NEC];
    __shared__ float sb[NOUT];
    for (int i = threadIdx.x; i < NOUT*NEC; i += 256) w[i] = e2w[i];
    if (threadIdx.x < NOUT) sb[threadIdx.x] = e2b[threadIdx.x];
    __syncthreads();

    int warp = threadIdx.x >> 5, lane = threadIdx.x & 31;
    int row = blockIdx.x*8 + warp;
    const float* e1r = g_e1 + (size_t)row*NEC;
    float r[16];
    #pragma unroll
    for (int k = 0; k < 16; k++) r[k] = e1r[lane + k*32];
    int b = row >> 11, v = row & (NV-1);
    #pragma unroll
    for (int o = 0; o < NOUT; o++) {
        float s = 0.f;
        #pragma unroll
        for (int k = 0; k < 16; k++) s += r[k]*w[o*NEC + lane + k*32];
        #pragma unroll
        for (int off = 16; off; off >>= 1) s += __shfl_xor_sync(0xffffffffu, s, off);
        if (lane == 0) out[((size_t)b*NOUT + o)*NV + v] = s + sb[o];
    }
}

// ---------------- launch ----------------
extern "C" void kernel_launch(void* const* d_in, const int* in_sizes, int n_in,
                              void* d_out, int out_size)
{
    (void)in_sizes; (void)n_in; (void)out_size;
    const float* x    = (const float*)d_in[0];
    const float* A    = (const float*)d_in[1];
    const float* nv1  = (const float*)d_in[2];
    const float* nv2  = (const float*)d_in[3];
    const float* fw   = (const float*)d_in[4];
    const float* fb   = (const float*)d_in[5];
    const float* gw   = (const float*)d_in[6];
    const float* gb   = (const float*)d_in[7];
    const float* sw   = (const float*)d_in[8];
    const float* sb   = (const float*)d_in[9];
    const float* gcnw = (const float*)d_in[10];
    const float* gcnb = (const float*)d_in[11];
    const float* bng  = (const float*)d_in[12];
    const float* bnb  = (const float*)d_in[13];
    const float* bnm  = (const float*)d_in[14];
    const float* bnv  = (const float*)d_in[15];
    const float* stw  = (const float*)d_in[16];
    const float* stb  = (const float*)d_in[17];
    const float* e1w  = (const float*)d_in[18];
    const float* e1b  = (const float*)d_in[19];
    const float* e2w  = (const float*)d_in[20];
    const float* e2b  = (const float*)d_in[21];

    __half *p_gx, *p_H, *p_skt, *p_w1r, *p_bt, *p_gxl, *p_wsk;
    float  *p_e1, *p_bsk;
    cudaGetSymbolAddress((void**)&p_gx,   g_gx);
    cudaGetSymbolAddress((void**)&p_H,    g_H);
    cudaGetSymbolAddress((void**)&p_skt,  g_skt);
    cudaGetSymbolAddress((void**)&p_e1,   g_e1);
    cudaGetSymbolAddress((void**)&p_w1r,  g_w1r);
    cudaGetSymbolAddress((void**)&p_bt,   g_bt);
    cudaGetSymbolAddress((void**)&p_gxl,  g_gxl);
    cudaGetSymbolAddress((void**)&p_wsk,  g_wsk);
    cudaGetSymbolAddress((void**)&p_bsk,  g_bsk);

    cudaFuncSetAttribute(mma_gemm, cudaFuncAttributeMaxDynamicSharedMemorySize, GSMEM);

    adp_kernel<<<NV, 256>>>(nv1, nv2);
    bt_kernel<<<dim3(NV/32, NV/32, 3), 256>>>(A);
    gw_prep<<<(NLAY*224*32)/256, 256>>>(gcnw);
    wsk_prep<<<(NSC*NSC)/256, 256>>>(sw, sb);
    wf_prep<<<(NLAY*64*64)/256, 256>>>(fw, gw);
    start_kernel<<<dim3(NV/256, 13, NB), 256>>>(x, stw, stb);

    const int dil[NLAY] = {1,2,1,2,1,2,1,2};
    int Tin = 13, parity = 0;
    for (int i = 0; i < NLAY; i++) {
        int d = dil[i], Tout = Tin - d;
        gated_mma<<<dim3(NV/128, Tout, NB), 256>>>(fb, gb, i, Tin, d, parity);

        if (i < NLAY-1) {   // last layer's gcn output is dead code
            int M = NB*NRC*Tout;
            // hop 1: gx @ A_z -> H0, H2, H4
            mma_gemm<<<dim3(NV/BN, M/BM, 3), 256, GSMEM>>>(
                p_gx, p_bt, p_H,
                0L, (long)NN, 2L*HBUF,
                NV, NV, NV, NV/BK, nullptr, 4);
            // hop 2: H{0,2,4} @ A_z -> H1, H3, H5
            mma_gemm<<<dim3(NV/BN, M/BM, 3), 256, GSMEM>>>(
                p_H, p_bt, p_H + HBUF,
                2L*HBUF, (long)NN, 2L*HBUF,
                NV, NV, NV, NV/BK, nullptr, 4);
            gcn_kernel<<<dim3(NV/64, Tout, NB), 256>>>(gcnb, bng, bnb, bnm, bnv,
                                                       i, Tin, d, parity);
        }
        parity ^= 1;
        Tin = Tout;
    }

    // skt[bv][j] = relu(gxl[bv][:] . wsk[j][:] + bsk[j])  (fp16 out)
    mma_gemm<<<dim3(NSC/BN, (NB*NV)/BM, 1), 256, GSMEM>>>(
        p_gxl, p_wsk, p_skt,
        0L, 0L, 0L,
        NSC, NSC, NSC, NSC/BK, p_bsk, 1|4);
    w1r_kernel<<<(NEC*NSC)/256, 256>>>(e1w);
    // E1 = relu(skt @ e1w^T + b1)
    mma_gemm<<<dim3(NEC/BN, (NB*NV)/BM, 1), 256, GSMEM>>>(
        p_skt, p_w1r, p_e1,
        0L, 0L, 0L,
        NSC, NSC, NEC, NSC/BK, e1b, 1);
    end2_kernel<<<(NB*NV)/8, 256>>>(e2w, e2b, (float*)d_out);
}